// round 8
// baseline (speedup 1.0000x reference)
#include <cuda_runtime.h>
#include <cuda_bf16.h>
#include <cstdint>

#define N_NODES 50000
#define NPAD    50176         // 196*256, padded rows for unguarded tile loads
#define E_EDGES 800000
#define D       256
#define R_REL   8
#define B_BAS   4
#define KTOT    1280
#define KPAIR   640           // bf16 pairs per A/W row
#define SCB     196           // scan blocks

// ------------------------------------------------------------------
// Scratch (device globals). A stored pre-split: hi/lo bf16 pairs.
// ------------------------------------------------------------------
__device__ __align__(16) uint32_t g_ah1[(size_t)NPAD * KPAIR];
__device__ __align__(16) uint32_t g_al1[(size_t)NPAD * KPAIR];
__device__ __align__(16) uint32_t g_ah2[(size_t)NPAD * KPAIR];
__device__ __align__(16) uint32_t g_al2[(size_t)NPAD * KPAIR];
__device__ __align__(16) uint32_t g_wbh[(size_t)D * KPAIR];
__device__ __align__(16) uint32_t g_wbl[(size_t)D * KPAIR];
__device__ __align__(16) float    g_norm[N_NODES * R_REL];
__device__ __align__(16) int      g_cnt [N_NODES * R_REL];
__device__ __align__(16) int      g_deg [N_NODES];
__device__ __align__(16) int      g_part[256];
__device__ __align__(16) int      g_rowptr[N_NODES + 1];
__device__ __align__(16) int      g_wcur[N_NODES];
__device__ __align__(16) int      g_epack[E_EDGES];

// ------------------------------------------------------------------
// helpers
// ------------------------------------------------------------------
__device__ __forceinline__ uint32_t smem_u32(const void* p) {
    uint32_t a;
    asm("{ .reg .u64 t; cvta.to.shared.u64 t, %1; cvt.u32.u64 %0, t; }"
        : "=r"(a) : "l"(p));
    return a;
}

__device__ __forceinline__ void split2(float a, float b, uint32_t& h, uint32_t& l) {
    __nv_bfloat162 hh = __floats2bfloat162_rn(a, b);
    float la = a - __bfloat162float(hh.x);
    float lb = b - __bfloat162float(hh.y);
    __nv_bfloat162 ll = __floats2bfloat162_rn(la, lb);
    h = *(uint32_t*)&hh;
    l = *(uint32_t*)&ll;
}

__device__ __forceinline__ float2 upk2(uint32_t h, uint32_t l) {
    float2 a = __bfloat1622float2(*(__nv_bfloat162*)&h);
    float2 b = __bfloat1622float2(*(__nv_bfloat162*)&l);
    return make_float2(a.x + b.x, a.y + b.y);
}

__device__ __forceinline__ void cp16(uint32_t dst, const void* src) {
    asm volatile("cp.async.cg.shared.global [%0], [%1], 16;" :: "r"(dst), "l"(src));
}

__device__ __forceinline__ void ldsm_x4(uint32_t* r, uint32_t a) {
    asm volatile("ldmatrix.sync.aligned.m8n8.x4.shared.b16 {%0,%1,%2,%3}, [%4];"
        : "=r"(r[0]), "=r"(r[1]), "=r"(r[2]), "=r"(r[3]) : "r"(a));
}

__device__ __forceinline__ void ldsm_x2(uint32_t& r0, uint32_t& r1, uint32_t a) {
    asm volatile("ldmatrix.sync.aligned.m8n8.x2.shared.b16 {%0,%1}, [%2];"
        : "=r"(r0), "=r"(r1) : "r"(a));
}

__device__ __forceinline__ void mma_bf16(float* c, const uint32_t* a,
                                         uint32_t b0, uint32_t b1) {
    asm volatile(
        "mma.sync.aligned.m16n8k16.row.col.f32.bf16.bf16.f32 "
        "{%0,%1,%2,%3}, {%4,%5,%6,%7}, {%8,%9}, {%0,%1,%2,%3};"
        : "+f"(c[0]), "+f"(c[1]), "+f"(c[2]), "+f"(c[3])
        : "r"(a[0]), "r"(a[1]), "r"(a[2]), "r"(a[3]), "r"(b0), "r"(b1));
}

// ------------------------------------------------------------------
// Graph prep
// ------------------------------------------------------------------
__global__ void zero_cnt_k() {
    int i = blockIdx.x * blockDim.x + threadIdx.x;
    if (i < N_NODES * R_REL) g_cnt[i] = 0;
}

__global__ void count_k(const int* __restrict__ ei, const int* __restrict__ et) {
    int e = blockIdx.x * blockDim.x + threadIdx.x;
    if (e >= E_EDGES) return;
    atomicAdd(&g_cnt[ei[E_EDGES + e] * R_REL + et[e]], 1);
}

__global__ void norm_deg_k() {
    int i = blockIdx.x * blockDim.x + threadIdx.x;
    if (i >= N_NODES) return;
    int deg = 0;
#pragma unroll
    for (int r = 0; r < R_REL; r++) {
        int c = g_cnt[i * R_REL + r];
        g_norm[i * R_REL + r] = 1.0f / (float)(c > 0 ? c : 1);
        deg += c;
    }
    g_deg[i] = deg;
}

__global__ void partial_k() {
    __shared__ int s[256];
    int b = blockIdx.x, t = threadIdx.x, i = b * 256 + t;
    s[t] = (i < N_NODES) ? g_deg[i] : 0;
    __syncthreads();
    for (int o = 128; o > 0; o >>= 1) {
        if (t < o) s[t] += s[t + o];
        __syncthreads();
    }
    if (t == 0) g_part[b] = s[0];
}

__global__ void scanp_k() {
    __shared__ int s[256];
    int t = threadIdx.x;
    s[t] = (t < SCB) ? g_part[t] : 0;
    __syncthreads();
    for (int o = 1; o < 256; o <<= 1) {
        int v = (t >= o) ? s[t - o] : 0;
        __syncthreads();
        s[t] += v;
        __syncthreads();
    }
    g_part[t] = (t == 0) ? 0 : s[t - 1];
}

__global__ void rowptr_k() {
    __shared__ int s[256];
    int b = blockIdx.x, t = threadIdx.x, i = b * 256 + t;
    int d = (i < N_NODES) ? g_deg[i] : 0;
    s[t] = d;
    __syncthreads();
    for (int o = 1; o < 256; o <<= 1) {
        int v = (t >= o) ? s[t - o] : 0;
        __syncthreads();
        s[t] += v;
        __syncthreads();
    }
    int excl = g_part[b] + s[t] - d;
    if (i < N_NODES) { g_rowptr[i] = excl; g_wcur[i] = excl; }
    if (i == N_NODES - 1) g_rowptr[N_NODES] = excl + d;
}

__global__ void scatter_k(const int* __restrict__ ei, const int* __restrict__ et) {
    int e = blockIdx.x * blockDim.x + threadIdx.x;
    if (e >= E_EDGES) return;
    int src = ei[e];
    int dst = ei[E_EDGES + e];
    int r   = et[e];
    int pos = atomicAdd(&g_wcur[dst], 1);
    g_epack[pos] = src | (r << 16);
}

__global__ void copy_feat_k(const float* __restrict__ x) {
    int id = blockIdx.x * blockDim.x + threadIdx.x;
    if (id >= N_NODES * 128) return;
    int row = id >> 7, p = id & 127;
    float2 v = *(const float2*)(x + (size_t)row * D + p * 2);
    uint32_t h, l;
    split2(v.x, v.y, h, l);
    g_ah1[(size_t)row * KPAIR + 512 + p] = h;
    g_al1[(size_t)row * KPAIR + 512 + p] = l;
}

__global__ void prep_w_k(const float* __restrict__ basis,
                         const float* __restrict__ root) {
    int id = blockIdx.x * blockDim.x + threadIdx.x;
    if (id >= D * KPAIR) return;
    int n = id / KPAIR, kk = id % KPAIR;
    int k0 = kk * 2;
    float x0 = (k0 < 1024) ? basis[(size_t)k0 * D + n]
                           : root[(size_t)(k0 - 1024) * D + n];
    float x1 = (k0 + 1 < 1024) ? basis[(size_t)(k0 + 1) * D + n]
                               : root[(size_t)(k0 + 1 - 1024) * D + n];
    uint32_t h, l;
    split2(x0, x1, h, l);
    g_wbh[id] = h;
    g_wbl[id] = l;
}

// ------------------------------------------------------------------
// CSR edge aggregation: one warp per dst.
// Warp-batched epack via shfl + feature prefetch + norm select-tree.
// ------------------------------------------------------------------
__global__ __launch_bounds__(256)
void edge_agg_k(const float* __restrict__ comp, int sel) {
    uint32_t* gah = sel ? g_ah2 : g_ah1;
    uint32_t* gal = sel ? g_al2 : g_al1;
    __shared__ float comp_s[R_REL * B_BAS];
    if (threadIdx.x < R_REL * B_BAS) comp_s[threadIdx.x] = comp[threadIdx.x];
    __syncthreads();

    int dst  = (blockIdx.x * 256 + threadIdx.x) >> 5;
    int lane = threadIdx.x & 31;
    if (dst >= N_NODES) return;

    int e0 = g_rowptr[dst], e1 = g_rowptr[dst + 1];
    float4 nA = *(const float4*)(g_norm + dst * R_REL);
    float4 nB = *(const float4*)(g_norm + dst * R_REL + 4);

    float acc[B_BAS][8];
#pragma unroll
    for (int b = 0; b < B_BAS; b++)
#pragma unroll
        for (int k = 0; k < 8; k++) acc[b][k] = 0.0f;

    const uint32_t foff = 512 + lane * 4;

    for (int eb = e0; eb < e1; eb += 32) {
        int cnt = min(32, e1 - eb);
        int myp = (eb + lane < e1) ? g_epack[eb + lane] : 0;

        int p = __shfl_sync(0xFFFFFFFFu, myp, 0);
        size_t fo = (size_t)(p & 0xFFFF) * KPAIR + foff;
        uint4 hq = *(const uint4*)(gah + fo);
        uint4 lq = *(const uint4*)(gal + fo);

        for (int j = 0; j < cnt; j++) {
            int pn = 0;
            uint4 hqn, lqn;
            if (j + 1 < cnt) {
                pn = __shfl_sync(0xFFFFFFFFu, myp, j + 1);
                size_t fon = (size_t)(pn & 0xFFFF) * KPAIR + foff;
                hqn = *(const uint4*)(gah + fon);
                lqn = *(const uint4*)(gal + fon);
            }
            int r = p >> 16;
            float w = (r < 4) ? ((r < 2) ? (r == 0 ? nA.x : nA.y)
                                         : (r == 2 ? nA.z : nA.w))
                              : ((r < 6) ? (r == 4 ? nB.x : nB.y)
                                         : (r == 6 ? nB.z : nB.w));
            float2 v0 = upk2(hq.x, lq.x), v1 = upk2(hq.y, lq.y);
            float2 v2 = upk2(hq.z, lq.z), v3 = upk2(hq.w, lq.w);
            const float* cr = comp_s + r * B_BAS;
#pragma unroll
            for (int b = 0; b < B_BAS; b++) {
                float c = cr[b] * w;
                acc[b][0] += c * v0.x; acc[b][1] += c * v0.y;
                acc[b][2] += c * v1.x; acc[b][3] += c * v1.y;
                acc[b][4] += c * v2.x; acc[b][5] += c * v2.y;
                acc[b][6] += c * v3.x; acc[b][7] += c * v3.y;
            }
            p = pn; hq = hqn; lq = lqn;
        }
    }

#pragma unroll
    for (int b = 0; b < B_BAS; b++) {
        uint4 hv, lv;
        split2(acc[b][0], acc[b][1], hv.x, lv.x);
        split2(acc[b][2], acc[b][3], hv.y, lv.y);
        split2(acc[b][4], acc[b][5], hv.z, lv.z);
        split2(acc[b][6], acc[b][7], hv.w, lv.w);
        size_t to = (size_t)dst * KPAIR + b * 128 + lane * 4;
        *(uint4*)(gah + to) = hv;
        *(uint4*)(gal + to) = lv;
    }
}

// ------------------------------------------------------------------
// bf16 3-term GEMM, cp.async 2-stage, single sync per chunk.
// ------------------------------------------------------------------
#define SSTR 20
#define ASZ  (128 * SSTR)
#define GSMEM (8 * ASZ * 4)     // 81920 B

__global__ __launch_bounds__(256, 2)
void gemm_k(int aSel, float* __restrict__ outExt, int mode,
            const float* __restrict__ bias, int M) {
    extern __shared__ uint32_t smem[];
    uint32_t sb = smem_u32(smem);

    const uint32_t* gah = aSel ? g_ah2 : g_ah1;
    const uint32_t* gal = aSel ? g_al2 : g_al1;

    int tid  = threadIdx.x;
    int wid  = tid >> 5, lane = tid & 31;
    int gq   = lane >> 2, t4 = lane & 3;
    int warp_m = wid & 3, warp_n = wid >> 2;
    int row0 = blockIdx.y * 128, c0 = blockIdx.x * 128;

    int rA = (lane & 7) + ((lane >> 3) & 1) * 8;
    int qA = (lane >> 4) * 4;
    int rB = lane & 7;
    int hB = ((lane >> 3) & 1) * 4;

    float acc[2][8][4];
#pragma unroll
    for (int mb = 0; mb < 2; mb++)
#pragma unroll
        for (int nb = 0; nb < 8; nb++)
#pragma unroll
            for (int c = 0; c < 4; c++) acc[mb][nb][c] = 0.0f;

#define PREFETCH(kc, buf) do {                                                \
    int _kc = (kc), _b = (buf);                                               \
    uint32_t bA  = sb + (uint32_t)((_b * 4 + 0) * ASZ) * 4;                   \
    uint32_t bAl = sb + (uint32_t)((_b * 4 + 1) * ASZ) * 4;                   \
    uint32_t bB  = sb + (uint32_t)((_b * 4 + 2) * ASZ) * 4;                   \
    uint32_t bBl = sb + (uint32_t)((_b * 4 + 3) * ASZ) * 4;                   \
    _Pragma("unroll")                                                         \
    for (int f = 0; f < 2; f++) {                                             \
        int id = tid + f * 256;                                               \
        int row = id >> 2, q = id & 3;                                        \
        uint32_t doff = (uint32_t)(row * SSTR + q * 4) * 4;                   \
        size_t ga = (size_t)(row0 + row) * KPAIR + _kc * 16 + q * 4;          \
        cp16(bA + doff, gah + ga);                                            \
        cp16(bAl + doff, gal + ga);                                           \
        size_t gb = (size_t)(c0 + row) * KPAIR + _kc * 16 + q * 4;            \
        cp16(bB + doff, g_wbh + gb);                                          \
        cp16(bBl + doff, g_wbl + gb);                                         \
    }                                                                         \
} while (0)

    const int NC = KPAIR / 16;   // 40
    PREFETCH(0, 0);
    asm volatile("cp.async.commit_group;" ::: "memory");

    for (int kc = 0; kc < NC; kc++) {
        // wait for this chunk's data (only group kc can be pending for us here)
        asm volatile("cp.async.wait_group 0;" ::: "memory");
        __syncthreads();   // data visible to all; also: all warps done with buf (kc+1)&1

        if (kc + 1 < NC) {
            PREFETCH(kc + 1, (kc + 1) & 1);   // overlaps with compute below
            asm volatile("cp.async.commit_group;" ::: "memory");
        }

        int buf = kc & 1;
        uint32_t bAH = sb + (uint32_t)((buf * 4 + 0) * ASZ) * 4;
        uint32_t bAL = sb + (uint32_t)((buf * 4 + 1) * ASZ) * 4;
        uint32_t bBH = sb + (uint32_t)((buf * 4 + 2) * ASZ) * 4;
        uint32_t bBL = sb + (uint32_t)((buf * 4 + 3) * ASZ) * 4;

#pragma unroll
        for (int s = 0; s < 2; s++) {
            uint32_t ah[2][4], al[2][4];
#pragma unroll
            for (int mb = 0; mb < 2; mb++) {
                uint32_t off = (uint32_t)((warp_m * 32 + mb * 16 + rA) * SSTR
                                          + s * 8 + qA) * 4;
                ldsm_x4(ah[mb], bAH + off);
                ldsm_x4(al[mb], bAL + off);
            }
#pragma unroll
            for (int nb = 0; nb < 8; nb++) {
                uint32_t offb = (uint32_t)((warp_n * 64 + nb * 8 + rB) * SSTR
                                           + s * 8 + hB) * 4;
                uint32_t bh0, bh1, bl0, bl1;
                ldsm_x2(bh0, bh1, bBH + offb);
                ldsm_x2(bl0, bl1, bBL + offb);
#pragma unroll
                for (int mb = 0; mb < 2; mb++) {
                    mma_bf16(acc[mb][nb], ah[mb], bh0, bh1);
                    mma_bf16(acc[mb][nb], ah[mb], bl0, bl1);
                    mma_bf16(acc[mb][nb], al[mb], bh0, bh1);
                }
            }
        }
        __syncthreads();   // all reads of buf done before it is refilled at kc+2
    }

    // ---- epilogue ----
#pragma unroll
    for (int nb = 0; nb < 8; nb++) {
        int coll = warp_n * 64 + nb * 8 + t4 * 2;
        float2 bv = *(const float2*)(bias + c0 + coll);
#pragma unroll
        for (int mb = 0; mb < 2; mb++) {
            int r0 = row0 + warp_m * 32 + mb * 16 + gq;
            int r1 = r0 + 8;
            float x0 = acc[mb][nb][0] + bv.x, x1 = acc[mb][nb][1] + bv.y;
            float x2 = acc[mb][nb][2] + bv.x, x3 = acc[mb][nb][3] + bv.y;
            if (mode == 1) {
                x0 = fmaxf(x0, 0.f); x1 = fmaxf(x1, 0.f);
                x2 = fmaxf(x2, 0.f); x3 = fmaxf(x3, 0.f);
                int p = (1024 + c0 + coll) >> 1;
                uint32_t h, l;
                if (r0 < M) {
                    split2(x0, x1, h, l);
                    g_ah2[(size_t)r0 * KPAIR + p] = h;
                    g_al2[(size_t)r0 * KPAIR + p] = l;
                }
                if (r1 < M) {
                    split2(x2, x3, h, l);
                    g_ah2[(size_t)r1 * KPAIR + p] = h;
                    g_al2[(size_t)r1 * KPAIR + p] = l;
                }
            } else {
                if (r0 < M) *(float2*)(outExt + (size_t)r0 * D + c0 + coll) = make_float2(x0, x1);
                if (r1 < M) *(float2*)(outExt + (size_t)r1 * D + c0 + coll) = make_float2(x2, x3);
            }
        }
    }
}

// ------------------------------------------------------------------
extern "C" void kernel_launch(void* const* d_in, const int* in_sizes, int n_in,
                              void* d_out, int out_size) {
    const float* x      = (const float*)d_in[0];
    const int*   ei     = (const int*)d_in[1];
    const int*   et     = (const int*)d_in[2];
    const float* basis1 = (const float*)d_in[3];
    const float* comp1  = (const float*)d_in[4];
    const float* root1  = (const float*)d_in[5];
    const float* bias1  = (const float*)d_in[6];
    const float* basis2 = (const float*)d_in[7];
    const float* comp2  = (const float*)d_in[8];
    const float* root2  = (const float*)d_in[9];
    const float* bias2  = (const float*)d_in[10];
    float* out = (float*)d_out;

    cudaFuncSetAttribute(gemm_k, cudaFuncAttributeMaxDynamicSharedMemorySize, GSMEM);

    const int T = 256;

    zero_cnt_k<<<(N_NODES * R_REL + T - 1) / T, T>>>();
    count_k<<<(E_EDGES + T - 1) / T, T>>>(ei, et);
    norm_deg_k<<<(N_NODES + T - 1) / T, T>>>();
    partial_k<<<SCB, 256>>>();
    scanp_k<<<1, 256>>>();
    rowptr_k<<<SCB, 256>>>();
    scatter_k<<<(E_EDGES + T - 1) / T, T>>>(ei, et);
    copy_feat_k<<<(N_NODES * 128 + T - 1) / T, T>>>(x);

    dim3 gG(2, (N_NODES + 127) / 128);
    int aggBlocks = (N_NODES * 32 + T - 1) / T;
    int wBlocks   = (D * KPAIR + T - 1) / T;

    // ---------------- layer 1 ----------------
    prep_w_k<<<wBlocks, T>>>(basis1, root1);
    edge_agg_k<<<aggBlocks, T>>>(comp1, 0);
    gemm_k<<<gG, T, GSMEM>>>(0, nullptr, 1, bias1, N_NODES);

    // ---------------- layer 2 ----------------
    prep_w_k<<<wBlocks, T>>>(basis2, root2);
    edge_agg_k<<<aggBlocks, T>>>(comp2, 1);
    gemm_k<<<gG, T, GSMEM>>>(1, out, 0, bias2, N_NODES);
}

// round 9
// speedup vs baseline: 1.0791x; 1.0791x over previous
#include <cuda_runtime.h>
#include <cuda_bf16.h>
#include <cstdint>

#define N_NODES 50000
#define NPAD    50176         // 196*256, padded rows for unguarded tile loads
#define E_EDGES 800000
#define D       256
#define R_REL   8
#define B_BAS   4
#define KTOT    1280
#define KPAIR   640           // bf16 pairs per A/W row
#define SCB     196           // scan blocks

// ------------------------------------------------------------------
// Scratch (device globals). A stored pre-split: hi/lo bf16 pairs.
// ------------------------------------------------------------------
__device__ __align__(16) uint32_t g_ah1[(size_t)NPAD * KPAIR];
__device__ __align__(16) uint32_t g_al1[(size_t)NPAD * KPAIR];
__device__ __align__(16) uint32_t g_ah2[(size_t)NPAD * KPAIR];
__device__ __align__(16) uint32_t g_al2[(size_t)NPAD * KPAIR];
__device__ __align__(16) uint32_t g_wbh[(size_t)D * KPAIR];
__device__ __align__(16) uint32_t g_wbl[(size_t)D * KPAIR];
__device__ __align__(16) float    g_norm[N_NODES * R_REL];
__device__ __align__(16) int      g_cnt [N_NODES * R_REL];
__device__ __align__(16) int      g_deg [N_NODES];
__device__ __align__(16) int      g_part[256];
__device__ __align__(16) int      g_rowptr[N_NODES + 1];
__device__ __align__(16) int      g_wcur[N_NODES];
__device__ __align__(16) int      g_epack[E_EDGES];

// ------------------------------------------------------------------
// helpers
// ------------------------------------------------------------------
__device__ __forceinline__ uint32_t smem_u32(const void* p) {
    uint32_t a;
    asm("{ .reg .u64 t; cvta.to.shared.u64 t, %1; cvt.u32.u64 %0, t; }"
        : "=r"(a) : "l"(p));
    return a;
}

__device__ __forceinline__ void split2(float a, float b, uint32_t& h, uint32_t& l) {
    __nv_bfloat162 hh = __floats2bfloat162_rn(a, b);
    float la = a - __bfloat162float(hh.x);
    float lb = b - __bfloat162float(hh.y);
    __nv_bfloat162 ll = __floats2bfloat162_rn(la, lb);
    h = *(uint32_t*)&hh;
    l = *(uint32_t*)&ll;
}

__device__ __forceinline__ float2 upk2(uint32_t h, uint32_t l) {
    float2 a = __bfloat1622float2(*(__nv_bfloat162*)&h);
    float2 b = __bfloat1622float2(*(__nv_bfloat162*)&l);
    return make_float2(a.x + b.x, a.y + b.y);
}

__device__ __forceinline__ void cp16(uint32_t dst, const void* src) {
    asm volatile("cp.async.cg.shared.global [%0], [%1], 16;" :: "r"(dst), "l"(src));
}

__device__ __forceinline__ void st_cs4(uint32_t* p, uint4 v) {
    asm volatile("st.global.cs.v4.u32 [%0], {%1,%2,%3,%4};"
                 :: "l"(p), "r"(v.x), "r"(v.y), "r"(v.z), "r"(v.w) : "memory");
}

__device__ __forceinline__ void ldsm_x4(uint32_t* r, uint32_t a) {
    asm volatile("ldmatrix.sync.aligned.m8n8.x4.shared.b16 {%0,%1,%2,%3}, [%4];"
        : "=r"(r[0]), "=r"(r[1]), "=r"(r[2]), "=r"(r[3]) : "r"(a));
}

__device__ __forceinline__ void ldsm_x2(uint32_t& r0, uint32_t& r1, uint32_t a) {
    asm volatile("ldmatrix.sync.aligned.m8n8.x2.shared.b16 {%0,%1}, [%2];"
        : "=r"(r0), "=r"(r1) : "r"(a));
}

__device__ __forceinline__ void mma_bf16(float* c, const uint32_t* a,
                                         uint32_t b0, uint32_t b1) {
    asm volatile(
        "mma.sync.aligned.m16n8k16.row.col.f32.bf16.bf16.f32 "
        "{%0,%1,%2,%3}, {%4,%5,%6,%7}, {%8,%9}, {%0,%1,%2,%3};"
        : "+f"(c[0]), "+f"(c[1]), "+f"(c[2]), "+f"(c[3])
        : "r"(a[0]), "r"(a[1]), "r"(a[2]), "r"(a[3]), "r"(b0), "r"(b1));
}

// ------------------------------------------------------------------
// Graph prep
// ------------------------------------------------------------------
__global__ void zero_cnt_k() {
    int i = blockIdx.x * blockDim.x + threadIdx.x;
    if (i < N_NODES * R_REL) g_cnt[i] = 0;
}

__global__ void count_k(const int* __restrict__ ei, const int* __restrict__ et) {
    int e = blockIdx.x * blockDim.x + threadIdx.x;
    if (e >= E_EDGES) return;
    atomicAdd(&g_cnt[ei[E_EDGES + e] * R_REL + et[e]], 1);
}

// norm + deg + per-block partial sum (merged)
__global__ void ndp_k() {
    __shared__ int s[256];
    int b = blockIdx.x, t = threadIdx.x, i = b * 256 + t;
    int deg = 0;
    if (i < N_NODES) {
#pragma unroll
        for (int r = 0; r < R_REL; r++) {
            int c = g_cnt[i * R_REL + r];
            g_norm[i * R_REL + r] = 1.0f / (float)(c > 0 ? c : 1);
            deg += c;
        }
        g_deg[i] = deg;
    }
    s[t] = deg;
    __syncthreads();
    for (int o = 128; o > 0; o >>= 1) {
        if (t < o) s[t] += s[t + o];
        __syncthreads();
    }
    if (t == 0) g_part[b] = s[0];
}

__global__ void scanp_k() {
    __shared__ int s[256];
    int t = threadIdx.x;
    s[t] = (t < SCB) ? g_part[t] : 0;
    __syncthreads();
    for (int o = 1; o < 256; o <<= 1) {
        int v = (t >= o) ? s[t - o] : 0;
        __syncthreads();
        s[t] += v;
        __syncthreads();
    }
    g_part[t] = (t == 0) ? 0 : s[t - 1];
}

__global__ void rowptr_k() {
    __shared__ int s[256];
    int b = blockIdx.x, t = threadIdx.x, i = b * 256 + t;
    int d = (i < N_NODES) ? g_deg[i] : 0;
    s[t] = d;
    __syncthreads();
    for (int o = 1; o < 256; o <<= 1) {
        int v = (t >= o) ? s[t - o] : 0;
        __syncthreads();
        s[t] += v;
        __syncthreads();
    }
    int excl = g_part[b] + s[t] - d;
    if (i < N_NODES) { g_rowptr[i] = excl; g_wcur[i] = excl; }
    if (i == N_NODES - 1) g_rowptr[N_NODES] = excl + d;
}

__global__ void scatter_k(const int* __restrict__ ei, const int* __restrict__ et) {
    int e = blockIdx.x * blockDim.x + threadIdx.x;
    if (e >= E_EDGES) return;
    int src = ei[e];
    int dst = ei[E_EDGES + e];
    int r   = et[e];
    int pos = atomicAdd(&g_wcur[dst], 1);
    g_epack[pos] = src | (r << 16);
}

__global__ void copy_feat_k(const float* __restrict__ x) {
    int id = blockIdx.x * blockDim.x + threadIdx.x;
    if (id >= N_NODES * 128) return;
    int row = id >> 7, p = id & 127;
    float2 v = *(const float2*)(x + (size_t)row * D + p * 2);
    uint32_t h, l;
    split2(v.x, v.y, h, l);
    g_ah1[(size_t)row * KPAIR + 512 + p] = h;
    g_al1[(size_t)row * KPAIR + 512 + p] = l;
}

__global__ void prep_w_k(const float* __restrict__ basis,
                         const float* __restrict__ root) {
    int id = blockIdx.x * blockDim.x + threadIdx.x;
    if (id >= D * KPAIR) return;
    int n = id / KPAIR, kk = id % KPAIR;
    int k0 = kk * 2;
    float x0 = (k0 < 1024) ? basis[(size_t)k0 * D + n]
                           : root[(size_t)(k0 - 1024) * D + n];
    float x1 = (k0 + 1 < 1024) ? basis[(size_t)(k0 + 1) * D + n]
                               : root[(size_t)(k0 + 1 - 1024) * D + n];
    uint32_t h, l;
    split2(x0, x1, h, l);
    g_wbh[id] = h;
    g_wbl[id] = l;
}

// ------------------------------------------------------------------
// CSR edge aggregation: one warp per dst. Simple loop (R7-winning
// form) + norm preload/select + 2-edge unroll + streaming t stores.
// ------------------------------------------------------------------
__device__ __forceinline__ float norm_sel(float4 nA, float4 nB, int r) {
    return (r < 4) ? ((r < 2) ? (r == 0 ? nA.x : nA.y)
                              : (r == 2 ? nA.z : nA.w))
                   : ((r < 6) ? (r == 4 ? nB.x : nB.y)
                              : (r == 6 ? nB.z : nB.w));
}

__global__ __launch_bounds__(256)
void edge_agg_k(const float* __restrict__ comp, int sel) {
    uint32_t* gah = sel ? g_ah2 : g_ah1;
    uint32_t* gal = sel ? g_al2 : g_al1;
    __shared__ float comp_s[R_REL * B_BAS];
    if (threadIdx.x < R_REL * B_BAS) comp_s[threadIdx.x] = comp[threadIdx.x];
    __syncthreads();

    int dst  = (blockIdx.x * 256 + threadIdx.x) >> 5;
    int lane = threadIdx.x & 31;
    if (dst >= N_NODES) return;

    int e0 = g_rowptr[dst], e1 = g_rowptr[dst + 1];
    float4 nA = *(const float4*)(g_norm + dst * R_REL);
    float4 nB = *(const float4*)(g_norm + dst * R_REL + 4);

    float acc[B_BAS][8];
#pragma unroll
    for (int b = 0; b < B_BAS; b++)
#pragma unroll
        for (int k = 0; k < 8; k++) acc[b][k] = 0.0f;

    const uint32_t foff = 512 + lane * 4;

    int e = e0;
    for (; e + 2 <= e1; e += 2) {
        int p0 = g_epack[e], p1 = g_epack[e + 1];
        size_t fo0 = (size_t)(p0 & 0xFFFF) * KPAIR + foff;
        size_t fo1 = (size_t)(p1 & 0xFFFF) * KPAIR + foff;
        uint4 hq0 = *(const uint4*)(gah + fo0);
        uint4 lq0 = *(const uint4*)(gal + fo0);
        uint4 hq1 = *(const uint4*)(gah + fo1);
        uint4 lq1 = *(const uint4*)(gal + fo1);

        int r0 = p0 >> 16, r1 = p1 >> 16;
        float w0 = norm_sel(nA, nB, r0), w1 = norm_sel(nA, nB, r1);
        float2 a0 = upk2(hq0.x, lq0.x), a1 = upk2(hq0.y, lq0.y);
        float2 a2 = upk2(hq0.z, lq0.z), a3 = upk2(hq0.w, lq0.w);
        float2 b0 = upk2(hq1.x, lq1.x), b1 = upk2(hq1.y, lq1.y);
        float2 b2 = upk2(hq1.z, lq1.z), b3 = upk2(hq1.w, lq1.w);
        const float* cr0 = comp_s + r0 * B_BAS;
        const float* cr1 = comp_s + r1 * B_BAS;
#pragma unroll
        for (int b = 0; b < B_BAS; b++) {
            float c0 = cr0[b] * w0, c1 = cr1[b] * w1;
            acc[b][0] += c0 * a0.x + c1 * b0.x;
            acc[b][1] += c0 * a0.y + c1 * b0.y;
            acc[b][2] += c0 * a1.x + c1 * b1.x;
            acc[b][3] += c0 * a1.y + c1 * b1.y;
            acc[b][4] += c0 * a2.x + c1 * b2.x;
            acc[b][5] += c0 * a2.y + c1 * b2.y;
            acc[b][6] += c0 * a3.x + c1 * b3.x;
            acc[b][7] += c0 * a3.y + c1 * b3.y;
        }
    }
    if (e < e1) {
        int p = g_epack[e];
        size_t fo = (size_t)(p & 0xFFFF) * KPAIR + foff;
        uint4 hq = *(const uint4*)(gah + fo);
        uint4 lq = *(const uint4*)(gal + fo);
        int r = p >> 16;
        float w = norm_sel(nA, nB, r);
        float2 v0 = upk2(hq.x, lq.x), v1 = upk2(hq.y, lq.y);
        float2 v2 = upk2(hq.z, lq.z), v3 = upk2(hq.w, lq.w);
        const float* cr = comp_s + r * B_BAS;
#pragma unroll
        for (int b = 0; b < B_BAS; b++) {
            float c = cr[b] * w;
            acc[b][0] += c * v0.x; acc[b][1] += c * v0.y;
            acc[b][2] += c * v1.x; acc[b][3] += c * v1.y;
            acc[b][4] += c * v2.x; acc[b][5] += c * v2.y;
            acc[b][6] += c * v3.x; acc[b][7] += c * v3.y;
        }
    }

#pragma unroll
    for (int b = 0; b < B_BAS; b++) {
        uint4 hv, lv;
        split2(acc[b][0], acc[b][1], hv.x, lv.x);
        split2(acc[b][2], acc[b][3], hv.y, lv.y);
        split2(acc[b][4], acc[b][5], hv.z, lv.z);
        split2(acc[b][6], acc[b][7], hv.w, lv.w);
        size_t to = (size_t)dst * KPAIR + b * 128 + lane * 4;
        st_cs4(gah + to, hv);           // streaming: don't evict feature region
        st_cs4(gal + to, lv);
    }
}

// ------------------------------------------------------------------
// bf16 3-term GEMM, cp.async 2-stage (exact 915.7-us version).
// ------------------------------------------------------------------
#define SSTR 20
#define ASZ  (128 * SSTR)
#define GSMEM (8 * ASZ * 4)     // 81920 B

__global__ __launch_bounds__(256, 2)
void gemm_k(int aSel, float* __restrict__ outExt, int mode,
            const float* __restrict__ bias, int M) {
    extern __shared__ uint32_t smem[];
    uint32_t sb = smem_u32(smem);

    const uint32_t* gah = aSel ? g_ah2 : g_ah1;
    const uint32_t* gal = aSel ? g_al2 : g_al1;

    int tid  = threadIdx.x;
    int wid  = tid >> 5, lane = tid & 31;
    int gq   = lane >> 2, t4 = lane & 3;
    int warp_m = wid & 3, warp_n = wid >> 2;
    int row0 = blockIdx.y * 128, c0 = blockIdx.x * 128;

    int rA = (lane & 7) + ((lane >> 3) & 1) * 8;
    int qA = (lane >> 4) * 4;
    int rB = lane & 7;
    int hB = ((lane >> 3) & 1) * 4;

    float acc[2][8][4];
#pragma unroll
    for (int mb = 0; mb < 2; mb++)
#pragma unroll
        for (int nb = 0; nb < 8; nb++)
#pragma unroll
            for (int c = 0; c < 4; c++) acc[mb][nb][c] = 0.0f;

#define PREFETCH(kc, buf) do {                                                \
    int _kc = (kc), _b = (buf);                                               \
    uint32_t bA  = sb + (uint32_t)((_b * 4 + 0) * ASZ) * 4;                   \
    uint32_t bAl = sb + (uint32_t)((_b * 4 + 1) * ASZ) * 4;                   \
    uint32_t bB  = sb + (uint32_t)((_b * 4 + 2) * ASZ) * 4;                   \
    uint32_t bBl = sb + (uint32_t)((_b * 4 + 3) * ASZ) * 4;                   \
    _Pragma("unroll")                                                         \
    for (int f = 0; f < 2; f++) {                                             \
        int id = tid + f * 256;                                               \
        int row = id >> 2, q = id & 3;                                        \
        uint32_t doff = (uint32_t)(row * SSTR + q * 4) * 4;                   \
        size_t ga = (size_t)(row0 + row) * KPAIR + _kc * 16 + q * 4;          \
        cp16(bA + doff, gah + ga);                                            \
        cp16(bAl + doff, gal + ga);                                           \
        size_t gb = (size_t)(c0 + row) * KPAIR + _kc * 16 + q * 4;            \
        cp16(bB + doff, g_wbh + gb);                                          \
        cp16(bBl + doff, g_wbl + gb);                                         \
    }                                                                         \
} while (0)

    const int NC = KPAIR / 16;   // 40
    PREFETCH(0, 0);
    asm volatile("cp.async.commit_group;" ::: "memory");

    for (int kc = 0; kc < NC; kc++) {
        if (kc + 1 < NC) {
            PREFETCH(kc + 1, (kc + 1) & 1);
            asm volatile("cp.async.commit_group;" ::: "memory");
            asm volatile("cp.async.wait_group 1;" ::: "memory");
        } else {
            asm volatile("cp.async.wait_group 0;" ::: "memory");
        }
        __syncthreads();

        int buf = kc & 1;
        uint32_t bAH = sb + (uint32_t)((buf * 4 + 0) * ASZ) * 4;
        uint32_t bAL = sb + (uint32_t)((buf * 4 + 1) * ASZ) * 4;
        uint32_t bBH = sb + (uint32_t)((buf * 4 + 2) * ASZ) * 4;
        uint32_t bBL = sb + (uint32_t)((buf * 4 + 3) * ASZ) * 4;

#pragma unroll
        for (int s = 0; s < 2; s++) {
            uint32_t ah[2][4], al[2][4];
#pragma unroll
            for (int mb = 0; mb < 2; mb++) {
                uint32_t off = (uint32_t)((warp_m * 32 + mb * 16 + rA) * SSTR
                                          + s * 8 + qA) * 4;
                ldsm_x4(ah[mb], bAH + off);
                ldsm_x4(al[mb], bAL + off);
            }
#pragma unroll
            for (int nb = 0; nb < 8; nb++) {
                uint32_t offb = (uint32_t)((warp_n * 64 + nb * 8 + rB) * SSTR
                                           + s * 8 + hB) * 4;
                uint32_t bh0, bh1, bl0, bl1;
                ldsm_x2(bh0, bh1, bBH + offb);
                ldsm_x2(bl0, bl1, bBL + offb);
#pragma unroll
                for (int mb = 0; mb < 2; mb++) {
                    mma_bf16(acc[mb][nb], ah[mb], bh0, bh1);
                    mma_bf16(acc[mb][nb], ah[mb], bl0, bl1);
                    mma_bf16(acc[mb][nb], al[mb], bh0, bh1);
                }
            }
        }
        __syncthreads();
    }

    // ---- epilogue ----
#pragma unroll
    for (int nb = 0; nb < 8; nb++) {
        int coll = warp_n * 64 + nb * 8 + t4 * 2;
        float2 bv = *(const float2*)(bias + c0 + coll);
#pragma unroll
        for (int mb = 0; mb < 2; mb++) {
            int r0 = row0 + warp_m * 32 + mb * 16 + gq;
            int r1 = r0 + 8;
            float x0 = acc[mb][nb][0] + bv.x, x1 = acc[mb][nb][1] + bv.y;
            float x2 = acc[mb][nb][2] + bv.x, x3 = acc[mb][nb][3] + bv.y;
            if (mode == 1) {
                x0 = fmaxf(x0, 0.f); x1 = fmaxf(x1, 0.f);
                x2 = fmaxf(x2, 0.f); x3 = fmaxf(x3, 0.f);
                int p = (1024 + c0 + coll) >> 1;
                uint32_t h, l;
                if (r0 < M) {
                    split2(x0, x1, h, l);
                    g_ah2[(size_t)r0 * KPAIR + p] = h;
                    g_al2[(size_t)r0 * KPAIR + p] = l;
                }
                if (r1 < M) {
                    split2(x2, x3, h, l);
                    g_ah2[(size_t)r1 * KPAIR + p] = h;
                    g_al2[(size_t)r1 * KPAIR + p] = l;
                }
            } else {
                if (r0 < M) *(float2*)(outExt + (size_t)r0 * D + c0 + coll) = make_float2(x0, x1);
                if (r1 < M) *(float2*)(outExt + (size_t)r1 * D + c0 + coll) = make_float2(x2, x3);
            }
        }
    }
}

// ------------------------------------------------------------------
extern "C" void kernel_launch(void* const* d_in, const int* in_sizes, int n_in,
                              void* d_out, int out_size) {
    const float* x      = (const float*)d_in[0];
    const int*   ei     = (const int*)d_in[1];
    const int*   et     = (const int*)d_in[2];
    const float* basis1 = (const float*)d_in[3];
    const float* comp1  = (const float*)d_in[4];
    const float* root1  = (const float*)d_in[5];
    const float* bias1  = (const float*)d_in[6];
    const float* basis2 = (const float*)d_in[7];
    const float* comp2  = (const float*)d_in[8];
    const float* root2  = (const float*)d_in[9];
    const float* bias2  = (const float*)d_in[10];
    float* out = (float*)d_out;

    cudaFuncSetAttribute(gemm_k, cudaFuncAttributeMaxDynamicSharedMemorySize, GSMEM);

    const int T = 256;

    zero_cnt_k<<<(N_NODES * R_REL + T - 1) / T, T>>>();
    count_k<<<(E_EDGES + T - 1) / T, T>>>(ei, et);
    ndp_k<<<SCB, 256>>>();
    scanp_k<<<1, 256>>>();
    rowptr_k<<<SCB, 256>>>();
    scatter_k<<<(E_EDGES + T - 1) / T, T>>>(ei, et);
    copy_feat_k<<<(N_NODES * 128 + T - 1) / T, T>>>(x);

    dim3 gG(2, (N_NODES + 127) / 128);
    int aggBlocks = (N_NODES * 32 + T - 1) / T;
    int wBlocks   = (D * KPAIR + T - 1) / T;

    // ---------------- layer 1 ----------------
    prep_w_k<<<wBlocks, T>>>(basis1, root1);
    edge_agg_k<<<aggBlocks, T>>>(comp1, 0);
    gemm_k<<<gG, T, GSMEM>>>(0, nullptr, 1, bias1, N_NODES);

    // ---------------- layer 2 ----------------
    prep_w_k<<<wBlocks, T>>>(basis2, root2);
    edge_agg_k<<<aggBlocks, T>>>(comp2, 1);
    gemm_k<<<gG, T, GSMEM>>>(1, out, 0, bias2, N_NODES);
}

// round 10
// speedup vs baseline: 1.5129x; 1.4020x over previous
#include <cuda_runtime.h>
#include <cuda_fp16.h>
#include <cstdint>

#define N_NODES 50000
#define NPAD    50176
#define E_EDGES 800000
#define D       256
#define R_REL   8
#define B_BAS   4
#define KTOT    1280
#define KPAIR   640           // fp16 pairs per A/W row
#define SCB     196

// ------------------------------------------------------------------
// Scratch. A stored as SINGLE fp16 pairs (t region pairs 0..511,
// feature region pairs 512..639). W stored fp16 hi+lo.
// ------------------------------------------------------------------
__device__ __align__(16) uint32_t g_ah1[(size_t)NPAD * KPAIR];
__device__ __align__(16) uint32_t g_ah2[(size_t)NPAD * KPAIR];
__device__ __align__(16) uint32_t g_wbh[(size_t)D * KPAIR];
__device__ __align__(16) uint32_t g_wbl[(size_t)D * KPAIR];
__device__ __align__(16) float    g_norm[N_NODES * R_REL];
__device__ __align__(16) int      g_cnt [N_NODES * R_REL];
__device__ __align__(16) int      g_deg [N_NODES];
__device__ __align__(16) int      g_part[256];
__device__ __align__(16) int      g_rowptr[N_NODES + 1];
__device__ __align__(16) int      g_wcur[N_NODES];
__device__ __align__(16) int      g_epack[E_EDGES];

// ------------------------------------------------------------------
// helpers
// ------------------------------------------------------------------
__device__ __forceinline__ uint32_t smem_u32(const void* p) {
    uint32_t a;
    asm("{ .reg .u64 t; cvta.to.shared.u64 t, %1; cvt.u32.u64 %0, t; }"
        : "=r"(a) : "l"(p));
    return a;
}

__device__ __forceinline__ uint32_t packh2(float a, float b) {
    __half2 h = __floats2half2_rn(a, b);
    return *(uint32_t*)&h;
}

__device__ __forceinline__ float2 unph2(uint32_t u) {
    return __half22float2(*(__half2*)&u);
}

__device__ __forceinline__ void cp16(uint32_t dst, const void* src) {
    asm volatile("cp.async.cg.shared.global [%0], [%1], 16;" :: "r"(dst), "l"(src));
}

__device__ __forceinline__ void st_cs4(uint32_t* p, uint4 v) {
    asm volatile("st.global.cs.v4.u32 [%0], {%1,%2,%3,%4};"
                 :: "l"(p), "r"(v.x), "r"(v.y), "r"(v.z), "r"(v.w) : "memory");
}

__device__ __forceinline__ void ldsm_x4(uint32_t* r, uint32_t a) {
    asm volatile("ldmatrix.sync.aligned.m8n8.x4.shared.b16 {%0,%1,%2,%3}, [%4];"
        : "=r"(r[0]), "=r"(r[1]), "=r"(r[2]), "=r"(r[3]) : "r"(a));
}

__device__ __forceinline__ void mma_f16(float* c, const uint32_t* a,
                                        uint32_t b0, uint32_t b1) {
    asm volatile(
        "mma.sync.aligned.m16n8k16.row.col.f32.f16.f16.f32 "
        "{%0,%1,%2,%3}, {%4,%5,%6,%7}, {%8,%9}, {%0,%1,%2,%3};"
        : "+f"(c[0]), "+f"(c[1]), "+f"(c[2]), "+f"(c[3])
        : "r"(a[0]), "r"(a[1]), "r"(a[2]), "r"(a[3]), "r"(b0), "r"(b1));
}

// ------------------------------------------------------------------
// Graph prep (unchanged from 915.7-us version, ndp merged)
// ------------------------------------------------------------------
__global__ void zero_cnt_k() {
    int i = blockIdx.x * blockDim.x + threadIdx.x;
    if (i < N_NODES * R_REL) g_cnt[i] = 0;
}

__global__ void count_k(const int* __restrict__ ei, const int* __restrict__ et) {
    int e = blockIdx.x * blockDim.x + threadIdx.x;
    if (e >= E_EDGES) return;
    atomicAdd(&g_cnt[ei[E_EDGES + e] * R_REL + et[e]], 1);
}

__global__ void ndp_k() {
    __shared__ int s[256];
    int b = blockIdx.x, t = threadIdx.x, i = b * 256 + t;
    int deg = 0;
    if (i < N_NODES) {
#pragma unroll
        for (int r = 0; r < R_REL; r++) {
            int c = g_cnt[i * R_REL + r];
            g_norm[i * R_REL + r] = 1.0f / (float)(c > 0 ? c : 1);
            deg += c;
        }
        g_deg[i] = deg;
    }
    s[t] = deg;
    __syncthreads();
    for (int o = 128; o > 0; o >>= 1) {
        if (t < o) s[t] += s[t + o];
        __syncthreads();
    }
    if (t == 0) g_part[b] = s[0];
}

__global__ void scanp_k() {
    __shared__ int s[256];
    int t = threadIdx.x;
    s[t] = (t < SCB) ? g_part[t] : 0;
    __syncthreads();
    for (int o = 1; o < 256; o <<= 1) {
        int v = (t >= o) ? s[t - o] : 0;
        __syncthreads();
        s[t] += v;
        __syncthreads();
    }
    g_part[t] = (t == 0) ? 0 : s[t - 1];
}

__global__ void rowptr_k() {
    __shared__ int s[256];
    int b = blockIdx.x, t = threadIdx.x, i = b * 256 + t;
    int d = (i < N_NODES) ? g_deg[i] : 0;
    s[t] = d;
    __syncthreads();
    for (int o = 1; o < 256; o <<= 1) {
        int v = (t >= o) ? s[t - o] : 0;
        __syncthreads();
        s[t] += v;
        __syncthreads();
    }
    int excl = g_part[b] + s[t] - d;
    if (i < N_NODES) { g_rowptr[i] = excl; g_wcur[i] = excl; }
    if (i == N_NODES - 1) g_rowptr[N_NODES] = excl + d;
}

__global__ void scatter_k(const int* __restrict__ ei, const int* __restrict__ et) {
    int e = blockIdx.x * blockDim.x + threadIdx.x;
    if (e >= E_EDGES) return;
    int src = ei[e];
    int dst = ei[E_EDGES + e];
    int r   = et[e];
    int pos = atomicAdd(&g_wcur[dst], 1);
    g_epack[pos] = src | (r << 16);
}

// x -> fp16 pairs, feature region of A1
__global__ void copy_feat_k(const float* __restrict__ x) {
    int id = blockIdx.x * blockDim.x + threadIdx.x;
    if (id >= N_NODES * 128) return;
    int row = id >> 7, p = id & 127;
    float2 v = *(const float2*)(x + (size_t)row * D + p * 2);
    g_ah1[(size_t)row * KPAIR + 512 + p] = packh2(v.x, v.y);
}

// W[1280][256] -> fp16 hi + fp16 residual lo, n-major pairs
__global__ void prep_w_k(const float* __restrict__ basis,
                         const float* __restrict__ root) {
    int id = blockIdx.x * blockDim.x + threadIdx.x;
    if (id >= D * KPAIR) return;
    int n = id / KPAIR, kk = id % KPAIR;
    int k0 = kk * 2;
    float x0 = (k0 < 1024) ? basis[(size_t)k0 * D + n]
                           : root[(size_t)(k0 - 1024) * D + n];
    float x1 = (k0 + 1 < 1024) ? basis[(size_t)(k0 + 1) * D + n]
                               : root[(size_t)(k0 + 1 - 1024) * D + n];
    __half2 h = __floats2half2_rn(x0, x1);
    float l0 = x0 - __half2float(h.x);
    float l1 = x1 - __half2float(h.y);
    g_wbh[id] = *(uint32_t*)&h;
    g_wbl[id] = packh2(l0, l1);
}

// ------------------------------------------------------------------
// CSR edge aggregation: one warp per dst. fp16 features (1 uint4/edge).
// ------------------------------------------------------------------
__device__ __forceinline__ float norm_sel(float4 nA, float4 nB, int r) {
    return (r < 4) ? ((r < 2) ? (r == 0 ? nA.x : nA.y)
                              : (r == 2 ? nA.z : nA.w))
                   : ((r < 6) ? (r == 4 ? nB.x : nB.y)
                              : (r == 6 ? nB.z : nB.w));
}

__global__ __launch_bounds__(256)
void edge_agg_k(const float* __restrict__ comp, int sel) {
    uint32_t* gah = sel ? g_ah2 : g_ah1;
    __shared__ float comp_s[R_REL * B_BAS];
    if (threadIdx.x < R_REL * B_BAS) comp_s[threadIdx.x] = comp[threadIdx.x];
    __syncthreads();

    int dst  = (blockIdx.x * 256 + threadIdx.x) >> 5;
    int lane = threadIdx.x & 31;
    if (dst >= N_NODES) return;

    int e0 = g_rowptr[dst], e1 = g_rowptr[dst + 1];
    float4 nA = *(const float4*)(g_norm + dst * R_REL);
    float4 nB = *(const float4*)(g_norm + dst * R_REL + 4);

    float acc[B_BAS][8];
#pragma unroll
    for (int b = 0; b < B_BAS; b++)
#pragma unroll
        for (int k = 0; k < 8; k++) acc[b][k] = 0.0f;

    const uint32_t foff = 512 + lane * 4;

    int e = e0;
    for (; e + 2 <= e1; e += 2) {
        int p0 = g_epack[e], p1 = g_epack[e + 1];
        uint4 q0 = *(const uint4*)(gah + (size_t)(p0 & 0xFFFF) * KPAIR + foff);
        uint4 q1 = *(const uint4*)(gah + (size_t)(p1 & 0xFFFF) * KPAIR + foff);
        int r0 = p0 >> 16, r1 = p1 >> 16;
        float w0 = norm_sel(nA, nB, r0), w1 = norm_sel(nA, nB, r1);
        float2 a0 = unph2(q0.x), a1 = unph2(q0.y), a2 = unph2(q0.z), a3 = unph2(q0.w);
        float2 b0 = unph2(q1.x), b1 = unph2(q1.y), b2 = unph2(q1.z), b3 = unph2(q1.w);
        const float* cr0 = comp_s + r0 * B_BAS;
        const float* cr1 = comp_s + r1 * B_BAS;
#pragma unroll
        for (int b = 0; b < B_BAS; b++) {
            float c0 = cr0[b] * w0, c1 = cr1[b] * w1;
            acc[b][0] += c0 * a0.x + c1 * b0.x;
            acc[b][1] += c0 * a0.y + c1 * b0.y;
            acc[b][2] += c0 * a1.x + c1 * b1.x;
            acc[b][3] += c0 * a1.y + c1 * b1.y;
            acc[b][4] += c0 * a2.x + c1 * b2.x;
            acc[b][5] += c0 * a2.y + c1 * b2.y;
            acc[b][6] += c0 * a3.x + c1 * b3.x;
            acc[b][7] += c0 * a3.y + c1 * b3.y;
        }
    }
    if (e < e1) {
        int p = g_epack[e];
        uint4 q = *(const uint4*)(gah + (size_t)(p & 0xFFFF) * KPAIR + foff);
        int r = p >> 16;
        float w = norm_sel(nA, nB, r);
        float2 v0 = unph2(q.x), v1 = unph2(q.y), v2 = unph2(q.z), v3 = unph2(q.w);
        const float* cr = comp_s + r * B_BAS;
#pragma unroll
        for (int b = 0; b < B_BAS; b++) {
            float c = cr[b] * w;
            acc[b][0] += c * v0.x; acc[b][1] += c * v0.y;
            acc[b][2] += c * v1.x; acc[b][3] += c * v1.y;
            acc[b][4] += c * v2.x; acc[b][5] += c * v2.y;
            acc[b][6] += c * v3.x; acc[b][7] += c * v3.y;
        }
    }

#pragma unroll
    for (int b = 0; b < B_BAS; b++) {
        uint4 hv;
        hv.x = packh2(acc[b][0], acc[b][1]);
        hv.y = packh2(acc[b][2], acc[b][3]);
        hv.z = packh2(acc[b][4], acc[b][5]);
        hv.w = packh2(acc[b][6], acc[b][7]);
        st_cs4(gah + (size_t)dst * KPAIR + b * 128 + lane * 4, hv);
    }
}

// ------------------------------------------------------------------
// fp16 2-term GEMM: C = A(fp16) @ (Wh + Wl) + bias
// cp.async 2-stage, ldmatrix x4, mma m16n8k16.f16.
// ------------------------------------------------------------------
#define SSTR 20
#define ASZ  (128 * SSTR)
#define GSMEM (6 * ASZ * 4)     // 2 bufs x 3 arrays = 61440 B

__global__ __launch_bounds__(256, 2)
void gemm_k(int aSel, float* __restrict__ outExt, int mode,
            const float* __restrict__ bias, int M) {
    extern __shared__ uint32_t smem[];
    uint32_t sb = smem_u32(smem);

    const uint32_t* gah = aSel ? g_ah2 : g_ah1;

    int tid  = threadIdx.x;
    int wid  = tid >> 5, lane = tid & 31;
    int gq   = lane >> 2, t4 = lane & 3;
    int warp_m = wid & 3, warp_n = wid >> 2;
    int row0 = blockIdx.y * 128, c0 = blockIdx.x * 128;

    // A ldmatrix lane addressing (verified in passing R7 kernel)
    int rA = (lane & 7) + ((lane >> 3) & 1) * 8;
    int qA = (lane >> 4) * 4;
    // B ldmatrix x4 over nb-pairs: lanes 0-7 m0(nb,k0-7), 8-15 m1(nb,k8-15),
    // 16-23 m2(nb+1,k0-7), 24-31 m3(nb+1,k8-15)
    int rBrow = ((lane >> 4) & 1) * 8 + (lane & 7);   // row within nb-pair block
    int hB    = ((lane >> 3) & 1) * 4;                 // k-half (pairs)

    float acc[2][8][4];
#pragma unroll
    for (int mb = 0; mb < 2; mb++)
#pragma unroll
        for (int nb = 0; nb < 8; nb++)
#pragma unroll
            for (int c = 0; c < 4; c++) acc[mb][nb][c] = 0.0f;

#define PREFETCH(kc, buf) do {                                                \
    int _kc = (kc), _b = (buf);                                               \
    uint32_t bA  = sb + (uint32_t)((_b * 3 + 0) * ASZ) * 4;                   \
    uint32_t bBh = sb + (uint32_t)((_b * 3 + 1) * ASZ) * 4;                   \
    uint32_t bBl = sb + (uint32_t)((_b * 3 + 2) * ASZ) * 4;                   \
    _Pragma("unroll")                                                         \
    for (int f = 0; f < 2; f++) {                                             \
        int id = tid + f * 256;                                               \
        int row = id >> 2, q = id & 3;                                        \
        uint32_t doff = (uint32_t)(row * SSTR + q * 4) * 4;                   \
        size_t ga = (size_t)(row0 + row) * KPAIR + _kc * 16 + q * 4;          \
        cp16(bA + doff, gah + ga);                                            \
        size_t gb = (size_t)(c0 + row) * KPAIR + _kc * 16 + q * 4;            \
        cp16(bBh + doff, g_wbh + gb);                                         \
        cp16(bBl + doff, g_wbl + gb);                                         \
    }                                                                         \
} while (0)

    const int NC = KPAIR / 16;   // 40
    PREFETCH(0, 0);
    asm volatile("cp.async.commit_group;" ::: "memory");

    for (int kc = 0; kc < NC; kc++) {
        if (kc + 1 < NC) {
            PREFETCH(kc + 1, (kc + 1) & 1);
            asm volatile("cp.async.commit_group;" ::: "memory");
            asm volatile("cp.async.wait_group 1;" ::: "memory");
        } else {
            asm volatile("cp.async.wait_group 0;" ::: "memory");
        }
        __syncthreads();

        int buf = kc & 1;
        uint32_t bA  = sb + (uint32_t)((buf * 3 + 0) * ASZ) * 4;
        uint32_t bBH = sb + (uint32_t)((buf * 3 + 1) * ASZ) * 4;
        uint32_t bBL = sb + (uint32_t)((buf * 3 + 2) * ASZ) * 4;

#pragma unroll
        for (int s = 0; s < 2; s++) {
            uint32_t ah[2][4];
#pragma unroll
            for (int mb = 0; mb < 2; mb++) {
                uint32_t off = (uint32_t)((warp_m * 32 + mb * 16 + rA) * SSTR
                                          + s * 8 + qA) * 4;
                ldsm_x4(ah[mb], bA + off);
            }
#pragma unroll
            for (int nb2 = 0; nb2 < 4; nb2++) {
                uint32_t offb = (uint32_t)((warp_n * 64 + nb2 * 16 + rBrow) * SSTR
                                           + s * 8 + hB) * 4;
                uint32_t bh[4], bl[4];
                ldsm_x4(bh, bBH + offb);
                ldsm_x4(bl, bBL + offb);
#pragma unroll
                for (int half = 0; half < 2; half++) {
                    int nb = nb2 * 2 + half;
#pragma unroll
                    for (int mb = 0; mb < 2; mb++) {
                        mma_f16(acc[mb][nb], ah[mb], bh[half * 2], bh[half * 2 + 1]);
                        mma_f16(acc[mb][nb], ah[mb], bl[half * 2], bl[half * 2 + 1]);
                    }
                }
            }
        }
        __syncthreads();
    }

    // ---- epilogue ----
#pragma unroll
    for (int nb = 0; nb < 8; nb++) {
        int coll = warp_n * 64 + nb * 8 + t4 * 2;
        float2 bv = *(const float2*)(bias + c0 + coll);
#pragma unroll
        for (int mb = 0; mb < 2; mb++) {
            int r0 = row0 + warp_m * 32 + mb * 16 + gq;
            int r1 = r0 + 8;
            float x0 = acc[mb][nb][0] + bv.x, x1 = acc[mb][nb][1] + bv.y;
            float x2 = acc[mb][nb][2] + bv.x, x3 = acc[mb][nb][3] + bv.y;
            if (mode == 1) {   // relu, store h as fp16 pairs in A2 feature region
                x0 = fmaxf(x0, 0.f); x1 = fmaxf(x1, 0.f);
                x2 = fmaxf(x2, 0.f); x3 = fmaxf(x3, 0.f);
                int p = (1024 + c0 + coll) >> 1;
                if (r0 < M) g_ah2[(size_t)r0 * KPAIR + p] = packh2(x0, x1);
                if (r1 < M) g_ah2[(size_t)r1 * KPAIR + p] = packh2(x2, x3);
            } else {
                if (r0 < M) *(float2*)(outExt + (size_t)r0 * D + c0 + coll) = make_float2(x0, x1);
                if (r1 < M) *(float2*)(outExt + (size_t)r1 * D + c0 + coll) = make_float2(x2, x3);
            }
        }
    }
}

// ------------------------------------------------------------------
extern "C" void kernel_launch(void* const* d_in, const int* in_sizes, int n_in,
                              void* d_out, int out_size) {
    const float* x      = (const float*)d_in[0];
    const int*   ei     = (const int*)d_in[1];
    const int*   et     = (const int*)d_in[2];
    const float* basis1 = (const float*)d_in[3];
    const float* comp1  = (const float*)d_in[4];
    const float* root1  = (const float*)d_in[5];
    const float* bias1  = (const float*)d_in[6];
    const float* basis2 = (const float*)d_in[7];
    const float* comp2  = (const float*)d_in[8];
    const float* root2  = (const float*)d_in[9];
    const float* bias2  = (const float*)d_in[10];
    float* out = (float*)d_out;

    cudaFuncSetAttribute(gemm_k, cudaFuncAttributeMaxDynamicSharedMemorySize, GSMEM);

    const int T = 256;

    zero_cnt_k<<<(N_NODES * R_REL + T - 1) / T, T>>>();
    count_k<<<(E_EDGES + T - 1) / T, T>>>(ei, et);
    ndp_k<<<SCB, 256>>>();
    scanp_k<<<1, 256>>>();
    rowptr_k<<<SCB, 256>>>();
    scatter_k<<<(E_EDGES + T - 1) / T, T>>>(ei, et);
    copy_feat_k<<<(N_NODES * 128 + T - 1) / T, T>>>(x);

    dim3 gG(2, (N_NODES + 127) / 128);
    int aggBlocks = (N_NODES * 32 + T - 1) / T;
    int wBlocks   = (D * KPAIR + T - 1) / T;

    // ---------------- layer 1 ----------------
    prep_w_k<<<wBlocks, T>>>(basis1, root1);
    edge_agg_k<<<aggBlocks, T>>>(comp1, 0);
    gemm_k<<<gG, T, GSMEM>>>(0, nullptr, 1, bias1, N_NODES);

    // ---------------- layer 2 ----------------
    prep_w_k<<<wBlocks, T>>>(basis2, root2);
    edge_agg_k<<<aggBlocks, T>>>(comp2, 1);
    gemm_k<<<gG, T, GSMEM>>>(1, out, 0, bias2, N_NODES);
}

// round 11
// speedup vs baseline: 2.0536x; 1.3574x over previous
#include <cuda_runtime.h>
#include <cuda_fp16.h>
#include <cstdint>

#define N_NODES 50000
#define NPAD    50176
#define E_EDGES 800000
#define D       256
#define R_REL   8
#define B_BAS   4
#define KTOT    1280
#define KPAIR   640           // fp16 pairs per A/W row
#define SCB     196

// ------------------------------------------------------------------
// Scratch. A as single fp16 pairs (t pairs 0..511, features 512..639).
// W as single fp16 (hi only — precision budget spent deliberately).
// ------------------------------------------------------------------
__device__ __align__(16) uint32_t g_ah1[(size_t)NPAD * KPAIR];
__device__ __align__(16) uint32_t g_ah2[(size_t)NPAD * KPAIR];
__device__ __align__(16) uint32_t g_wbh[(size_t)D * KPAIR];
__device__ __align__(16) float    g_norm[N_NODES * R_REL];
__device__ __align__(16) int      g_cnt [N_NODES * R_REL];
__device__ __align__(16) int      g_deg [N_NODES];
__device__ __align__(16) int      g_part[256];
__device__ __align__(16) int      g_rowptr[N_NODES + 1];
__device__ __align__(16) int      g_wcur[N_NODES];
__device__ __align__(16) int      g_epack[E_EDGES];

// ------------------------------------------------------------------
// helpers
// ------------------------------------------------------------------
__device__ __forceinline__ uint32_t smem_u32(const void* p) {
    uint32_t a;
    asm("{ .reg .u64 t; cvta.to.shared.u64 t, %1; cvt.u32.u64 %0, t; }"
        : "=r"(a) : "l"(p));
    return a;
}

__device__ __forceinline__ uint32_t packh2(float a, float b) {
    __half2 h = __floats2half2_rn(a, b);
    return *(uint32_t*)&h;
}

__device__ __forceinline__ float2 unph2(uint32_t u) {
    return __half22float2(*(__half2*)&u);
}

__device__ __forceinline__ void cp16(uint32_t dst, const void* src) {
    asm volatile("cp.async.cg.shared.global [%0], [%1], 16;" :: "r"(dst), "l"(src));
}

__device__ __forceinline__ void st_cs4(uint32_t* p, uint4 v) {
    asm volatile("st.global.cs.v4.u32 [%0], {%1,%2,%3,%4};"
                 :: "l"(p), "r"(v.x), "r"(v.y), "r"(v.z), "r"(v.w) : "memory");
}

__device__ __forceinline__ void ldsm_x4(uint32_t* r, uint32_t a) {
    asm volatile("ldmatrix.sync.aligned.m8n8.x4.shared.b16 {%0,%1,%2,%3}, [%4];"
        : "=r"(r[0]), "=r"(r[1]), "=r"(r[2]), "=r"(r[3]) : "r"(a));
}

__device__ __forceinline__ void mma_f16(float* c, const uint32_t* a,
                                        uint32_t b0, uint32_t b1) {
    asm volatile(
        "mma.sync.aligned.m16n8k16.row.col.f32.f16.f16.f32 "
        "{%0,%1,%2,%3}, {%4,%5,%6,%7}, {%8,%9}, {%0,%1,%2,%3};"
        : "+f"(c[0]), "+f"(c[1]), "+f"(c[2]), "+f"(c[3])
        : "r"(a[0]), "r"(a[1]), "r"(a[2]), "r"(a[3]), "r"(b0), "r"(b1));
}

// ------------------------------------------------------------------
// Graph prep
// ------------------------------------------------------------------
__global__ void zero_cnt_k() {
    int i = blockIdx.x * blockDim.x + threadIdx.x;
    if (i < N_NODES * R_REL) g_cnt[i] = 0;
}

__global__ void count_k(const int* __restrict__ ei, const int* __restrict__ et) {
    int e = blockIdx.x * blockDim.x + threadIdx.x;
    if (e >= E_EDGES) return;
    atomicAdd(&g_cnt[ei[E_EDGES + e] * R_REL + et[e]], 1);
}

__global__ void ndp_k() {
    __shared__ int s[256];
    int b = blockIdx.x, t = threadIdx.x, i = b * 256 + t;
    int deg = 0;
    if (i < N_NODES) {
#pragma unroll
        for (int r = 0; r < R_REL; r++) {
            int c = g_cnt[i * R_REL + r];
            g_norm[i * R_REL + r] = 1.0f / (float)(c > 0 ? c : 1);
            deg += c;
        }
        g_deg[i] = deg;
    }
    s[t] = deg;
    __syncthreads();
    for (int o = 128; o > 0; o >>= 1) {
        if (t < o) s[t] += s[t + o];
        __syncthreads();
    }
    if (t == 0) g_part[b] = s[0];
}

__global__ void scanp_k() {
    __shared__ int s[256];
    int t = threadIdx.x;
    s[t] = (t < SCB) ? g_part[t] : 0;
    __syncthreads();
    for (int o = 1; o < 256; o <<= 1) {
        int v = (t >= o) ? s[t - o] : 0;
        __syncthreads();
        s[t] += v;
        __syncthreads();
    }
    g_part[t] = (t == 0) ? 0 : s[t - 1];
}

__global__ void rowptr_k() {
    __shared__ int s[256];
    int b = blockIdx.x, t = threadIdx.x, i = b * 256 + t;
    int d = (i < N_NODES) ? g_deg[i] : 0;
    s[t] = d;
    __syncthreads();
    for (int o = 1; o < 256; o <<= 1) {
        int v = (t >= o) ? s[t - o] : 0;
        __syncthreads();
        s[t] += v;
        __syncthreads();
    }
    int excl = g_part[b] + s[t] - d;
    if (i < N_NODES) { g_rowptr[i] = excl; g_wcur[i] = excl; }
    if (i == N_NODES - 1) g_rowptr[N_NODES] = excl + d;
}

__global__ void scatter_k(const int* __restrict__ ei, const int* __restrict__ et) {
    int e = blockIdx.x * blockDim.x + threadIdx.x;
    if (e >= E_EDGES) return;
    int src = ei[e];
    int dst = ei[E_EDGES + e];
    int r   = et[e];
    int pos = atomicAdd(&g_wcur[dst], 1);
    g_epack[pos] = src | (r << 16);
}

__global__ void copy_feat_k(const float* __restrict__ x) {
    int id = blockIdx.x * blockDim.x + threadIdx.x;
    if (id >= N_NODES * 128) return;
    int row = id >> 7, p = id & 127;
    float2 v = *(const float2*)(x + (size_t)row * D + p * 2);
    g_ah1[(size_t)row * KPAIR + 512 + p] = packh2(v.x, v.y);
}

// W[1280][256] -> fp16 (single), n-major pairs
__global__ void prep_w_k(const float* __restrict__ basis,
                         const float* __restrict__ root) {
    int id = blockIdx.x * blockDim.x + threadIdx.x;
    if (id >= D * KPAIR) return;
    int n = id / KPAIR, kk = id % KPAIR;
    int k0 = kk * 2;
    float x0 = (k0 < 1024) ? basis[(size_t)k0 * D + n]
                           : root[(size_t)(k0 - 1024) * D + n];
    float x1 = (k0 + 1 < 1024) ? basis[(size_t)(k0 + 1) * D + n]
                               : root[(size_t)(k0 + 1 - 1024) * D + n];
    g_wbh[id] = packh2(x0, x1);
}

// ------------------------------------------------------------------
// CSR edge aggregation (byte-identical to 653-us version)
// ------------------------------------------------------------------
__device__ __forceinline__ float norm_sel(float4 nA, float4 nB, int r) {
    return (r < 4) ? ((r < 2) ? (r == 0 ? nA.x : nA.y)
                              : (r == 2 ? nA.z : nA.w))
                   : ((r < 6) ? (r == 4 ? nB.x : nB.y)
                              : (r == 6 ? nB.z : nB.w));
}

__global__ __launch_bounds__(256)
void edge_agg_k(const float* __restrict__ comp, int sel) {
    uint32_t* gah = sel ? g_ah2 : g_ah1;
    __shared__ float comp_s[R_REL * B_BAS];
    if (threadIdx.x < R_REL * B_BAS) comp_s[threadIdx.x] = comp[threadIdx.x];
    __syncthreads();

    int dst  = (blockIdx.x * 256 + threadIdx.x) >> 5;
    int lane = threadIdx.x & 31;
    if (dst >= N_NODES) return;

    int e0 = g_rowptr[dst], e1 = g_rowptr[dst + 1];
    float4 nA = *(const float4*)(g_norm + dst * R_REL);
    float4 nB = *(const float4*)(g_norm + dst * R_REL + 4);

    float acc[B_BAS][8];
#pragma unroll
    for (int b = 0; b < B_BAS; b++)
#pragma unroll
        for (int k = 0; k < 8; k++) acc[b][k] = 0.0f;

    const uint32_t foff = 512 + lane * 4;

    int e = e0;
    for (; e + 2 <= e1; e += 2) {
        int p0 = g_epack[e], p1 = g_epack[e + 1];
        uint4 q0 = *(const uint4*)(gah + (size_t)(p0 & 0xFFFF) * KPAIR + foff);
        uint4 q1 = *(const uint4*)(gah + (size_t)(p1 & 0xFFFF) * KPAIR + foff);
        int r0 = p0 >> 16, r1 = p1 >> 16;
        float w0 = norm_sel(nA, nB, r0), w1 = norm_sel(nA, nB, r1);
        float2 a0 = unph2(q0.x), a1 = unph2(q0.y), a2 = unph2(q0.z), a3 = unph2(q0.w);
        float2 b0 = unph2(q1.x), b1 = unph2(q1.y), b2 = unph2(q1.z), b3 = unph2(q1.w);
        const float* cr0 = comp_s + r0 * B_BAS;
        const float* cr1 = comp_s + r1 * B_BAS;
#pragma unroll
        for (int b = 0; b < B_BAS; b++) {
            float c0 = cr0[b] * w0, c1 = cr1[b] * w1;
            acc[b][0] += c0 * a0.x + c1 * b0.x;
            acc[b][1] += c0 * a0.y + c1 * b0.y;
            acc[b][2] += c0 * a1.x + c1 * b1.x;
            acc[b][3] += c0 * a1.y + c1 * b1.y;
            acc[b][4] += c0 * a2.x + c1 * b2.x;
            acc[b][5] += c0 * a2.y + c1 * b2.y;
            acc[b][6] += c0 * a3.x + c1 * b3.x;
            acc[b][7] += c0 * a3.y + c1 * b3.y;
        }
    }
    if (e < e1) {
        int p = g_epack[e];
        uint4 q = *(const uint4*)(gah + (size_t)(p & 0xFFFF) * KPAIR + foff);
        int r = p >> 16;
        float w = norm_sel(nA, nB, r);
        float2 v0 = unph2(q.x), v1 = unph2(q.y), v2 = unph2(q.z), v3 = unph2(q.w);
        const float* cr = comp_s + r * B_BAS;
#pragma unroll
        for (int b = 0; b < B_BAS; b++) {
            float c = cr[b] * w;
            acc[b][0] += c * v0.x; acc[b][1] += c * v0.y;
            acc[b][2] += c * v1.x; acc[b][3] += c * v1.y;
            acc[b][4] += c * v2.x; acc[b][5] += c * v2.y;
            acc[b][6] += c * v3.x; acc[b][7] += c * v3.y;
        }
    }

#pragma unroll
    for (int b = 0; b < B_BAS; b++) {
        uint4 hv;
        hv.x = packh2(acc[b][0], acc[b][1]);
        hv.y = packh2(acc[b][2], acc[b][3]);
        hv.z = packh2(acc[b][4], acc[b][5]);
        hv.w = packh2(acc[b][6], acc[b][7]);
        st_cs4(gah + (size_t)dst * KPAIR + b * 128 + lane * 4, hv);
    }
}

// ------------------------------------------------------------------
// fp16 single-term GEMM: C = A(fp16) @ W(fp16) + bias
// cp.async 2-stage, ldmatrix x4, mma m16n8k16.f16.
// ------------------------------------------------------------------
#define SSTR 20
#define ASZ  (128 * SSTR)
#define GSMEM (4 * ASZ * 4)     // 2 bufs x 2 arrays = 40960 B

__global__ __launch_bounds__(256, 2)
void gemm_k(int aSel, float* __restrict__ outExt, int mode,
            const float* __restrict__ bias, int M) {
    extern __shared__ uint32_t smem[];
    uint32_t sb = smem_u32(smem);

    const uint32_t* gah = aSel ? g_ah2 : g_ah1;

    int tid  = threadIdx.x;
    int wid  = tid >> 5, lane = tid & 31;
    int gq   = lane >> 2, t4 = lane & 3;
    int warp_m = wid & 3, warp_n = wid >> 2;
    int row0 = blockIdx.y * 128, c0 = blockIdx.x * 128;

    int rA = (lane & 7) + ((lane >> 3) & 1) * 8;
    int qA = (lane >> 4) * 4;
    int rBrow = ((lane >> 4) & 1) * 8 + (lane & 7);
    int hB    = ((lane >> 3) & 1) * 4;

    float acc[2][8][4];
#pragma unroll
    for (int mb = 0; mb < 2; mb++)
#pragma unroll
        for (int nb = 0; nb < 8; nb++)
#pragma unroll
            for (int c = 0; c < 4; c++) acc[mb][nb][c] = 0.0f;

#define PREFETCH(kc, buf) do {                                                \
    int _kc = (kc), _b = (buf);                                               \
    uint32_t bA  = sb + (uint32_t)((_b * 2 + 0) * ASZ) * 4;                   \
    uint32_t bBh = sb + (uint32_t)((_b * 2 + 1) * ASZ) * 4;                   \
    _Pragma("unroll")                                                         \
    for (int f = 0; f < 2; f++) {                                             \
        int id = tid + f * 256;                                               \
        int row = id >> 2, q = id & 3;                                        \
        uint32_t doff = (uint32_t)(row * SSTR + q * 4) * 4;                   \
        size_t ga = (size_t)(row0 + row) * KPAIR + _kc * 16 + q * 4;          \
        cp16(bA + doff, gah + ga);                                            \
        size_t gb = (size_t)(c0 + row) * KPAIR + _kc * 16 + q * 4;            \
        cp16(bBh + doff, g_wbh + gb);                                         \
    }                                                                         \
} while (0)

    const int NC = KPAIR / 16;   // 40
    PREFETCH(0, 0);
    asm volatile("cp.async.commit_group;" ::: "memory");

    for (int kc = 0; kc < NC; kc++) {
        if (kc + 1 < NC) {
            PREFETCH(kc + 1, (kc + 1) & 1);
            asm volatile("cp.async.commit_group;" ::: "memory");
            asm volatile("cp.async.wait_group 1;" ::: "memory");
        } else {
            asm volatile("cp.async.wait_group 0;" ::: "memory");
        }
        __syncthreads();

        int buf = kc & 1;
        uint32_t bA  = sb + (uint32_t)((buf * 2 + 0) * ASZ) * 4;
        uint32_t bBH = sb + (uint32_t)((buf * 2 + 1) * ASZ) * 4;

#pragma unroll
        for (int s = 0; s < 2; s++) {
            uint32_t ah[2][4];
#pragma unroll
            for (int mb = 0; mb < 2; mb++) {
                uint32_t off = (uint32_t)((warp_m * 32 + mb * 16 + rA) * SSTR
                                          + s * 8 + qA) * 4;
                ldsm_x4(ah[mb], bA + off);
            }
#pragma unroll
            for (int nb2 = 0; nb2 < 4; nb2++) {
                uint32_t offb = (uint32_t)((warp_n * 64 + nb2 * 16 + rBrow) * SSTR
                                           + s * 8 + hB) * 4;
                uint32_t bh[4];
                ldsm_x4(bh, bBH + offb);
#pragma unroll
                for (int half = 0; half < 2; half++) {
                    int nb = nb2 * 2 + half;
#pragma unroll
                    for (int mb = 0; mb < 2; mb++) {
                        mma_f16(acc[mb][nb], ah[mb], bh[half * 2], bh[half * 2 + 1]);
                    }
                }
            }
        }
        __syncthreads();
    }

    // ---- epilogue ----
#pragma unroll
    for (int nb = 0; nb < 8; nb++) {
        int coll = warp_n * 64 + nb * 8 + t4 * 2;
        float2 bv = *(const float2*)(bias + c0 + coll);
#pragma unroll
        for (int mb = 0; mb < 2; mb++) {
            int r0 = row0 + warp_m * 32 + mb * 16 + gq;
            int r1 = r0 + 8;
            float x0 = acc[mb][nb][0] + bv.x, x1 = acc[mb][nb][1] + bv.y;
            float x2 = acc[mb][nb][2] + bv.x, x3 = acc[mb][nb][3] + bv.y;
            if (mode == 1) {
                x0 = fmaxf(x0, 0.f); x1 = fmaxf(x1, 0.f);
                x2 = fmaxf(x2, 0.f); x3 = fmaxf(x3, 0.f);
                int p = (1024 + c0 + coll) >> 1;
                if (r0 < M) g_ah2[(size_t)r0 * KPAIR + p] = packh2(x0, x1);
                if (r1 < M) g_ah2[(size_t)r1 * KPAIR + p] = packh2(x2, x3);
            } else {
                if (r0 < M) *(float2*)(outExt + (size_t)r0 * D + c0 + coll) = make_float2(x0, x1);
                if (r1 < M) *(float2*)(outExt + (size_t)r1 * D + c0 + coll) = make_float2(x2, x3);
            }
        }
    }
}

// ------------------------------------------------------------------
extern "C" void kernel_launch(void* const* d_in, const int* in_sizes, int n_in,
                              void* d_out, int out_size) {
    const float* x      = (const float*)d_in[0];
    const int*   ei     = (const int*)d_in[1];
    const int*   et     = (const int*)d_in[2];
    const float* basis1 = (const float*)d_in[3];
    const float* comp1  = (const float*)d_in[4];
    const float* root1  = (const float*)d_in[5];
    const float* bias1  = (const float*)d_in[6];
    const float* basis2 = (const float*)d_in[7];
    const float* comp2  = (const float*)d_in[8];
    const float* root2  = (const float*)d_in[9];
    const float* bias2  = (const float*)d_in[10];
    float* out = (float*)d_out;

    cudaFuncSetAttribute(gemm_k, cudaFuncAttributeMaxDynamicSharedMemorySize, GSMEM);

    const int T = 256;

    zero_cnt_k<<<(N_NODES * R_REL + T - 1) / T, T>>>();
    count_k<<<(E_EDGES + T - 1) / T, T>>>(ei, et);
    ndp_k<<<SCB, 256>>>();
    scanp_k<<<1, 256>>>();
    rowptr_k<<<SCB, 256>>>();
    scatter_k<<<(E_EDGES + T - 1) / T, T>>>(ei, et);
    copy_feat_k<<<(N_NODES * 128 + T - 1) / T, T>>>(x);

    dim3 gG(2, (N_NODES + 127) / 128);
    int aggBlocks = (N_NODES * 32 + T - 1) / T;
    int wBlocks   = (D * KPAIR + T - 1) / T;

    // ---------------- layer 1 ----------------
    prep_w_k<<<wBlocks, T>>>(basis1, root1);
    edge_agg_k<<<aggBlocks, T>>>(comp1, 0);
    gemm_k<<<gG, T, GSMEM>>>(0, nullptr, 1, bias1, N_NODES);

    // ---------------- layer 2 ----------------
    prep_w_k<<<wBlocks, T>>>(basis2, root2);
    edge_agg_k<<<aggBlocks, T>>>(comp2, 1);
    gemm_k<<<gG, T, GSMEM>>>(1, out, 0, bias2, N_NODES);
}

// round 12
// speedup vs baseline: 2.2759x; 1.1082x over previous
#include <cuda_runtime.h>
#include <cuda_fp16.h>
#include <cstdint>

#define N_NODES 50000
#define NPAD    50176
#define E_EDGES 800000
#define D       256
#define R_REL   8
#define B_BAS   4
#define KPAIR   640           // fp16 pairs per A/W row
#define NR8     (N_NODES * R_REL)   // 400000 (dst,rel) bins
#define NB8     391                 // scan blocks of 1024 bins

// ------------------------------------------------------------------
// Scratch. A as single fp16 pairs (t pairs 0..511, features 512..639).
// W as single fp16. Edge lists sorted by (dst, rel).
// ------------------------------------------------------------------
__device__ __align__(16) uint32_t g_ah1[(size_t)NPAD * KPAIR];
__device__ __align__(16) uint32_t g_ah2[(size_t)NPAD * KPAIR];
__device__ __align__(16) uint32_t g_wbh[(size_t)D * KPAIR];
__device__ __align__(16) int      g_cnt [NR8];
__device__ __align__(16) int      g_part[512];
__device__ __align__(16) int      g_rowptr8[NR8 + 1];
__device__ __align__(16) int      g_wcur8[NR8];
__device__ __align__(16) int      g_esrc[E_EDGES];

// ------------------------------------------------------------------
// helpers
// ------------------------------------------------------------------
__device__ __forceinline__ uint32_t smem_u32(const void* p) {
    uint32_t a;
    asm("{ .reg .u64 t; cvta.to.shared.u64 t, %1; cvt.u32.u64 %0, t; }"
        : "=r"(a) : "l"(p));
    return a;
}

__device__ __forceinline__ uint32_t packh2(float a, float b) {
    __half2 h = __floats2half2_rn(a, b);
    return *(uint32_t*)&h;
}

__device__ __forceinline__ void cp16(uint32_t dst, const void* src) {
    asm volatile("cp.async.cg.shared.global [%0], [%1], 16;" :: "r"(dst), "l"(src));
}

__device__ __forceinline__ void st_cs4(uint32_t* p, uint4 v) {
    asm volatile("st.global.cs.v4.u32 [%0], {%1,%2,%3,%4};"
                 :: "l"(p), "r"(v.x), "r"(v.y), "r"(v.z), "r"(v.w) : "memory");
}

__device__ __forceinline__ void ldsm_x4(uint32_t* r, uint32_t a) {
    asm volatile("ldmatrix.sync.aligned.m8n8.x4.shared.b16 {%0,%1,%2,%3}, [%4];"
        : "=r"(r[0]), "=r"(r[1]), "=r"(r[2]), "=r"(r[3]) : "r"(a));
}

__device__ __forceinline__ void mma_f16(float* c, const uint32_t* a,
                                        uint32_t b0, uint32_t b1) {
    asm volatile(
        "mma.sync.aligned.m16n8k16.row.col.f32.f16.f16.f32 "
        "{%0,%1,%2,%3}, {%4,%5,%6,%7}, {%8,%9}, {%0,%1,%2,%3};"
        : "+f"(c[0]), "+f"(c[1]), "+f"(c[2]), "+f"(c[3])
        : "r"(a[0]), "r"(a[1]), "r"(a[2]), "r"(a[3]), "r"(b0), "r"(b1));
}

// ------------------------------------------------------------------
// Graph prep: CSR over (dst*8 + rel) bins
// ------------------------------------------------------------------
__global__ void zero_cnt_k() {
    int i = blockIdx.x * blockDim.x + threadIdx.x;
    if (i < NR8) g_cnt[i] = 0;
}

__global__ void count_k(const int* __restrict__ ei, const int* __restrict__ et) {
    int e = blockIdx.x * blockDim.x + threadIdx.x;
    if (e >= E_EDGES) return;
    atomicAdd(&g_cnt[ei[E_EDGES + e] * R_REL + et[e]], 1);
}

// per-block (1024 bins) partial sums
__global__ void partial8_k() {
    __shared__ int s[256];
    int b = blockIdx.x, t = threadIdx.x;
    int base = b * 1024 + t * 4;
    int sum = 0;
#pragma unroll
    for (int j = 0; j < 4; j++) {
        int idx = base + j;
        if (idx < NR8) sum += g_cnt[idx];
    }
    s[t] = sum;
    __syncthreads();
    for (int o = 128; o > 0; o >>= 1) {
        if (t < o) s[t] += s[t + o];
        __syncthreads();
    }
    if (t == 0) g_part[b] = s[0];
}

__global__ void scanp8_k() {
    __shared__ int s[512];
    int t = threadIdx.x;
    s[t] = (t < NB8) ? g_part[t] : 0;
    __syncthreads();
    for (int o = 1; o < 512; o <<= 1) {
        int v = (t >= o) ? s[t - o] : 0;
        __syncthreads();
        s[t] += v;
        __syncthreads();
    }
    g_part[t] = (t == 0) ? 0 : s[t - 1];
}

__global__ void rowptr8_k() {
    __shared__ int s[256];
    int b = blockIdx.x, t = threadIdx.x;
    int base = b * 1024 + t * 4;
    int v[4];
    int sum = 0;
#pragma unroll
    for (int j = 0; j < 4; j++) {
        int idx = base + j;
        v[j] = (idx < NR8) ? g_cnt[idx] : 0;
        sum += v[j];
    }
    s[t] = sum;
    __syncthreads();
    for (int o = 1; o < 256; o <<= 1) {
        int x = (t >= o) ? s[t - o] : 0;
        __syncthreads();
        s[t] += x;
        __syncthreads();
    }
    int run = g_part[b] + s[t] - sum;   // exclusive prefix for this thread
#pragma unroll
    for (int j = 0; j < 4; j++) {
        int idx = base + j;
        if (idx < NR8) {
            g_rowptr8[idx] = run;
            g_wcur8[idx]   = run;
            run += v[j];
            if (idx == NR8 - 1) g_rowptr8[NR8] = run;
        }
    }
}

__global__ void scatter8_k(const int* __restrict__ ei, const int* __restrict__ et) {
    int e = blockIdx.x * blockDim.x + threadIdx.x;
    if (e >= E_EDGES) return;
    int src = ei[e];
    int dst = ei[E_EDGES + e];
    int r   = et[e];
    int pos = atomicAdd(&g_wcur8[dst * R_REL + r], 1);
    g_esrc[pos] = src;
}

__global__ void copy_feat_k(const float* __restrict__ x) {
    int id = blockIdx.x * blockDim.x + threadIdx.x;
    if (id >= N_NODES * 128) return;
    int row = id >> 7, p = id & 127;
    float2 v = *(const float2*)(x + (size_t)row * D + p * 2);
    g_ah1[(size_t)row * KPAIR + 512 + p] = packh2(v.x, v.y);
}

// W[1280][256] -> fp16, n-major pairs
__global__ void prep_w_k(const float* __restrict__ basis,
                         const float* __restrict__ root) {
    int id = blockIdx.x * blockDim.x + threadIdx.x;
    if (id >= D * KPAIR) return;
    int n = id / KPAIR, kk = id % KPAIR;
    int k0 = kk * 2;
    float x0 = (k0 < 1024) ? basis[(size_t)k0 * D + n]
                           : root[(size_t)(k0 - 1024) * D + n];
    float x1 = (k0 + 1 < 1024) ? basis[(size_t)(k0 + 1) * D + n]
                               : root[(size_t)(k0 + 1 - 1024) * D + n];
    g_wbh[id] = packh2(x0, x1);
}

// ------------------------------------------------------------------
// Relation-grouped CSR aggregation: one warp per dst.
// Per relation: half2 partial sums (4 HADD2/edge), then one
// coefficient application (comp[r,b]/cnt) per non-empty relation.
// ------------------------------------------------------------------
__global__ __launch_bounds__(256)
void edge_agg_k(const float* __restrict__ comp, int sel) {
    uint32_t* gah = sel ? g_ah2 : g_ah1;
    __shared__ float comp_s[R_REL * B_BAS];
    if (threadIdx.x < R_REL * B_BAS) comp_s[threadIdx.x] = comp[threadIdx.x];
    __syncthreads();

    int dst  = (blockIdx.x * 256 + threadIdx.x) >> 5;
    int lane = threadIdx.x & 31;
    if (dst >= N_NODES) return;

    // 9 rowptr values for this dst, via lanes 0..8
    int rp = (lane <= 8) ? g_rowptr8[dst * R_REL + lane] : 0;

    float acc[B_BAS][8];
#pragma unroll
    for (int b = 0; b < B_BAS; b++)
#pragma unroll
        for (int k = 0; k < 8; k++) acc[b][k] = 0.0f;

    const uint32_t* featbase = gah + 512 + lane * 4;

    for (int r = 0; r < R_REL; r++) {
        int e0 = __shfl_sync(0xFFFFFFFFu, rp, r);
        int e1 = __shfl_sync(0xFFFFFFFFu, rp, r + 1);
        if (e0 >= e1) continue;

        __half2 p0 = __float2half2_rn(0.f), p1 = p0, p2 = p0, p3 = p0;
        int e = e0;
        for (; e + 2 <= e1; e += 2) {
            int s0 = g_esrc[e], s1 = g_esrc[e + 1];
            uint4 q0 = *(const uint4*)(featbase + (size_t)s0 * KPAIR);
            uint4 q1 = *(const uint4*)(featbase + (size_t)s1 * KPAIR);
            p0 = __hadd2(p0, *(__half2*)&q0.x);
            p1 = __hadd2(p1, *(__half2*)&q0.y);
            p2 = __hadd2(p2, *(__half2*)&q0.z);
            p3 = __hadd2(p3, *(__half2*)&q0.w);
            p0 = __hadd2(p0, *(__half2*)&q1.x);
            p1 = __hadd2(p1, *(__half2*)&q1.y);
            p2 = __hadd2(p2, *(__half2*)&q1.z);
            p3 = __hadd2(p3, *(__half2*)&q1.w);
        }
        if (e < e1) {
            int s0 = g_esrc[e];
            uint4 q0 = *(const uint4*)(featbase + (size_t)s0 * KPAIR);
            p0 = __hadd2(p0, *(__half2*)&q0.x);
            p1 = __hadd2(p1, *(__half2*)&q0.y);
            p2 = __hadd2(p2, *(__half2*)&q0.z);
            p3 = __hadd2(p3, *(__half2*)&q0.w);
        }

        float w = 1.0f / (float)(e1 - e0);   // norm, free from CSR
        float2 f0 = __half22float2(p0), f1 = __half22float2(p1);
        float2 f2 = __half22float2(p2), f3 = __half22float2(p3);
        const float* cr = comp_s + r * B_BAS;
#pragma unroll
        for (int b = 0; b < B_BAS; b++) {
            float c = cr[b] * w;
            acc[b][0] += c * f0.x; acc[b][1] += c * f0.y;
            acc[b][2] += c * f1.x; acc[b][3] += c * f1.y;
            acc[b][4] += c * f2.x; acc[b][5] += c * f2.y;
            acc[b][6] += c * f3.x; acc[b][7] += c * f3.y;
        }
    }

#pragma unroll
    for (int b = 0; b < B_BAS; b++) {
        uint4 hv;
        hv.x = packh2(acc[b][0], acc[b][1]);
        hv.y = packh2(acc[b][2], acc[b][3]);
        hv.z = packh2(acc[b][4], acc[b][5]);
        hv.w = packh2(acc[b][6], acc[b][7]);
        st_cs4(gah + (size_t)dst * KPAIR + b * 128 + lane * 4, hv);
    }
}

// ------------------------------------------------------------------
// fp16 single-term GEMM (byte-identical to 481-us version)
// ------------------------------------------------------------------
#define SSTR 20
#define ASZ  (128 * SSTR)
#define GSMEM (4 * ASZ * 4)     // 40960 B

__global__ __launch_bounds__(256, 2)
void gemm_k(int aSel, float* __restrict__ outExt, int mode,
            const float* __restrict__ bias, int M) {
    extern __shared__ uint32_t smem[];
    uint32_t sb = smem_u32(smem);

    const uint32_t* gah = aSel ? g_ah2 : g_ah1;

    int tid  = threadIdx.x;
    int wid  = tid >> 5, lane = tid & 31;
    int gq   = lane >> 2, t4 = lane & 3;
    int warp_m = wid & 3, warp_n = wid >> 2;
    int row0 = blockIdx.y * 128, c0 = blockIdx.x * 128;

    int rA = (lane & 7) + ((lane >> 3) & 1) * 8;
    int qA = (lane >> 4) * 4;
    int rBrow = ((lane >> 4) & 1) * 8 + (lane & 7);
    int hB    = ((lane >> 3) & 1) * 4;

    float acc[2][8][4];
#pragma unroll
    for (int mb = 0; mb < 2; mb++)
#pragma unroll
        for (int nb = 0; nb < 8; nb++)
#pragma unroll
            for (int c = 0; c < 4; c++) acc[mb][nb][c] = 0.0f;

#define PREFETCH(kc, buf) do {                                                \
    int _kc = (kc), _b = (buf);                                               \
    uint32_t bA  = sb + (uint32_t)((_b * 2 + 0) * ASZ) * 4;                   \
    uint32_t bBh = sb + (uint32_t)((_b * 2 + 1) * ASZ) * 4;                   \
    _Pragma("unroll")                                                         \
    for (int f = 0; f < 2; f++) {                                             \
        int id = tid + f * 256;                                               \
        int row = id >> 2, q = id & 3;                                        \
        uint32_t doff = (uint32_t)(row * SSTR + q * 4) * 4;                   \
        size_t ga = (size_t)(row0 + row) * KPAIR + _kc * 16 + q * 4;          \
        cp16(bA + doff, gah + ga);                                            \
        size_t gb = (size_t)(c0 + row) * KPAIR + _kc * 16 + q * 4;            \
        cp16(bBh + doff, g_wbh + gb);                                         \
    }                                                                         \
} while (0)

    const int NC = KPAIR / 16;   // 40
    PREFETCH(0, 0);
    asm volatile("cp.async.commit_group;" ::: "memory");

    for (int kc = 0; kc < NC; kc++) {
        if (kc + 1 < NC) {
            PREFETCH(kc + 1, (kc + 1) & 1);
            asm volatile("cp.async.commit_group;" ::: "memory");
            asm volatile("cp.async.wait_group 1;" ::: "memory");
        } else {
            asm volatile("cp.async.wait_group 0;" ::: "memory");
        }
        __syncthreads();

        int buf = kc & 1;
        uint32_t bA  = sb + (uint32_t)((buf * 2 + 0) * ASZ) * 4;
        uint32_t bBH = sb + (uint32_t)((buf * 2 + 1) * ASZ) * 4;

#pragma unroll
        for (int s = 0; s < 2; s++) {
            uint32_t ah[2][4];
#pragma unroll
            for (int mb = 0; mb < 2; mb++) {
                uint32_t off = (uint32_t)((warp_m * 32 + mb * 16 + rA) * SSTR
                                          + s * 8 + qA) * 4;
                ldsm_x4(ah[mb], bA + off);
            }
#pragma unroll
            for (int nb2 = 0; nb2 < 4; nb2++) {
                uint32_t offb = (uint32_t)((warp_n * 64 + nb2 * 16 + rBrow) * SSTR
                                           + s * 8 + hB) * 4;
                uint32_t bh[4];
                ldsm_x4(bh, bBH + offb);
#pragma unroll
                for (int half = 0; half < 2; half++) {
                    int nb = nb2 * 2 + half;
#pragma unroll
                    for (int mb = 0; mb < 2; mb++) {
                        mma_f16(acc[mb][nb], ah[mb], bh[half * 2], bh[half * 2 + 1]);
                    }
                }
            }
        }
        __syncthreads();
    }

    // ---- epilogue ----
#pragma unroll
    for (int nb = 0; nb < 8; nb++) {
        int coll = warp_n * 64 + nb * 8 + t4 * 2;
        float2 bv = *(const float2*)(bias + c0 + coll);
#pragma unroll
        for (int mb = 0; mb < 2; mb++) {
            int r0 = row0 + warp_m * 32 + mb * 16 + gq;
            int r1 = r0 + 8;
            float x0 = acc[mb][nb][0] + bv.x, x1 = acc[mb][nb][1] + bv.y;
            float x2 = acc[mb][nb][2] + bv.x, x3 = acc[mb][nb][3] + bv.y;
            if (mode == 1) {
                x0 = fmaxf(x0, 0.f); x1 = fmaxf(x1, 0.f);
                x2 = fmaxf(x2, 0.f); x3 = fmaxf(x3, 0.f);
                int p = (1024 + c0 + coll) >> 1;
                if (r0 < M) g_ah2[(size_t)r0 * KPAIR + p] = packh2(x0, x1);
                if (r1 < M) g_ah2[(size_t)r1 * KPAIR + p] = packh2(x2, x3);
            } else {
                if (r0 < M) *(float2*)(outExt + (size_t)r0 * D + c0 + coll) = make_float2(x0, x1);
                if (r1 < M) *(float2*)(outExt + (size_t)r1 * D + c0 + coll) = make_float2(x2, x3);
            }
        }
    }
}

// ------------------------------------------------------------------
extern "C" void kernel_launch(void* const* d_in, const int* in_sizes, int n_in,
                              void* d_out, int out_size) {
    const float* x      = (const float*)d_in[0];
    const int*   ei     = (const int*)d_in[1];
    const int*   et     = (const int*)d_in[2];
    const float* basis1 = (const float*)d_in[3];
    const float* comp1  = (const float*)d_in[4];
    const float* root1  = (const float*)d_in[5];
    const float* bias1  = (const float*)d_in[6];
    const float* basis2 = (const float*)d_in[7];
    const float* comp2  = (const float*)d_in[8];
    const float* root2  = (const float*)d_in[9];
    const float* bias2  = (const float*)d_in[10];
    float* out = (float*)d_out;

    cudaFuncSetAttribute(gemm_k, cudaFuncAttributeMaxDynamicSharedMemorySize, GSMEM);

    const int T = 256;

    zero_cnt_k<<<(NR8 + T - 1) / T, T>>>();
    count_k<<<(E_EDGES + T - 1) / T, T>>>(ei, et);
    partial8_k<<<NB8, 256>>>();
    scanp8_k<<<1, 512>>>();
    rowptr8_k<<<NB8, 256>>>();
    scatter8_k<<<(E_EDGES + T - 1) / T, T>>>(ei, et);
    copy_feat_k<<<(N_NODES * 128 + T - 1) / T, T>>>(x);

    dim3 gG(2, (N_NODES + 127) / 128);
    int aggBlocks = (N_NODES * 32 + T - 1) / T;
    int wBlocks   = (D * KPAIR + T - 1) / T;

    // ---------------- layer 1 ----------------
    prep_w_k<<<wBlocks, T>>>(basis1, root1);
    edge_agg_k<<<aggBlocks, T>>>(comp1, 0);
    gemm_k<<<gG, T, GSMEM>>>(0, nullptr, 1, bias1, N_NODES);

    // ---------------- layer 2 ----------------
    prep_w_k<<<wBlocks, T>>>(basis2, root2);
    edge_agg_k<<<aggBlocks, T>>>(comp2, 1);
    gemm_k<<<gG, T, GSMEM>>>(1, out, 0, bias2, N_NODES);
}